// round 14
// baseline (speedup 1.0000x reference)
#include <cuda_runtime.h>
#include <cuda_bf16.h>
#include <math.h>
#include <stdint.h>

// ---------------------------------------------------------------------------
// Problem constants
// ---------------------------------------------------------------------------
#define NW 1000
#define ND 100
#define NF 100
#define TIw 512
#define HDw 128

// Output layout (concatenated f32)
#define OFF_LAM   0
#define OFF_ZMAT  100
#define OFF_BETA  1000100
#define OFF_GAMMA 1001100
#define OFF_ETA   1001200
#define OFF_ZEV   1001300
#define OFF_H     101001300

#define KMAX 160

// ---------------------------------------------------------------------------
// Device scratch
// ---------------------------------------------------------------------------
__device__ __align__(16) float g_T1[NW * NF];
__device__ __align__(16) float g_T2[NW * NF];
__device__ __align__(16) float g_heli[NW * NF];
__device__ float g_y[NW];
__device__ float g_wp[NF];
__device__ int   g_kci[ND];

#define CSR_CAP 96
__device__ int   g_ccnt[NW];
__device__ int   g_ccol[NW * CSR_CAP];
__device__ float g_cval[NW * CSR_CAP];

__device__ __forceinline__ float warp_sum(float v) {
#pragma unroll
    for (int o = 16; o; o >>= 1) v += __shfl_xor_sync(0xffffffffu, v, o);
    return v;
}

__device__ __forceinline__ float load_scalar(const void* p) {
    int v = *(const int*)p;
    if (v >= 0 && v <= 1000000) return (float)v;
    return *(const float*)p;
}

// SpMM one row via CSR with shfl-broadcast (r10/r11 proven). Results in regs.
__device__ __forceinline__ void spmm_row_regs(const float* __restrict__ X,
                                              int row, int lane,
                                              float& a0, float& a1,
                                              float& a2, float& a3) {
    int nnz = g_ccnt[row];
    const int* cols = g_ccol + row * CSR_CAP;
    const float* vals = g_cval + row * CSR_CAP;
    int   c0 = (lane < nnz) ? cols[lane] : 0;
    float v0 = (lane < nnz) ? vals[lane] : 0.f;
    int   c1 = (lane + 32 < nnz) ? cols[lane + 32] : 0;
    float v1 = (lane + 32 < nnz) ? vals[lane + 32] : 0.f;
    int   c2 = (lane + 64 < nnz) ? cols[lane + 64] : 0;
    float v2 = (lane + 64 < nnz) ? vals[lane + 64] : 0.f;

    a0 = 0.f; a1 = 0.f; a2 = 0.f; a3 = 0.f;
    int lim0 = min(32, nnz);
    for (int s = 0; s < lim0; ++s) {
        int cc = __shfl_sync(0xffffffffu, c0, s);
        float vv = __shfl_sync(0xffffffffu, v0, s);
        const float* Xr = X + (size_t)cc * NF;
        a0 = fmaf(vv, Xr[lane], a0);
        a1 = fmaf(vv, Xr[lane + 32], a1);
        a2 = fmaf(vv, Xr[lane + 64], a2);
        if (lane < 4) a3 = fmaf(vv, Xr[lane + 96], a3);
    }
    if (nnz > 32) {
        int lim1 = min(32, nnz - 32);
        for (int s = 0; s < lim1; ++s) {
            int cc = __shfl_sync(0xffffffffu, c1, s);
            float vv = __shfl_sync(0xffffffffu, v1, s);
            const float* Xr = X + (size_t)cc * NF;
            a0 = fmaf(vv, Xr[lane], a0);
            a1 = fmaf(vv, Xr[lane + 32], a1);
            a2 = fmaf(vv, Xr[lane + 64], a2);
            if (lane < 4) a3 = fmaf(vv, Xr[lane + 96], a3);
        }
    }
    if (nnz > 64) {
        int lim2 = min(32, nnz - 64);
        for (int s = 0; s < lim2; ++s) {
            int cc = __shfl_sync(0xffffffffu, c2, s);
            float vv = __shfl_sync(0xffffffffu, v2, s);
            const float* Xr = X + (size_t)cc * NF;
            a0 = fmaf(vv, Xr[lane], a0);
            a1 = fmaf(vv, Xr[lane + 32], a1);
            a2 = fmaf(vv, Xr[lane + 64], a2);
            if (lane < 4) a3 = fmaf(vv, Xr[lane + 96], a3);
        }
    }
}

// ---------------------------------------------------------------------------
// Streams + events (static init; not during capture)
// ---------------------------------------------------------------------------
struct SideRes {
    cudaStream_t s_side, s_a, s_b;
    cudaEvent_t fork, ev_z, ev_t1, ev3, ev_beta, ev_final;
    SideRes() {
        int lo = 0, hi = 0;
        cudaDeviceGetStreamPriorityRange(&lo, &hi);
        cudaStreamCreateWithPriority(&s_side, cudaStreamNonBlocking, lo);
        cudaStreamCreateWithFlags(&s_a, cudaStreamNonBlocking);
        cudaStreamCreateWithFlags(&s_b, cudaStreamNonBlocking);
        cudaEventCreateWithFlags(&fork, cudaEventDisableTiming);
        cudaEventCreateWithFlags(&ev_z, cudaEventDisableTiming);
        cudaEventCreateWithFlags(&ev_t1, cudaEventDisableTiming);
        cudaEventCreateWithFlags(&ev3, cudaEventDisableTiming);
        cudaEventCreateWithFlags(&ev_beta, cudaEventDisableTiming);
        cudaEventCreateWithFlags(&ev_final, cudaEventDisableTiming);
    }
};
static SideRes g_sr;

// ---------------------------------------------------------------------------
// zev_zero — r10 proven shape (296 blk, 67.8us @ 61.8% DRAM), starts at t=0.
// ---------------------------------------------------------------------------
#define ZA4 (100u * 160u * 210u)
#define ZB4 (100u * 840u * 250u)
#define ZT4 (ZA4 + ZB4)

__global__ void __launch_bounds__(256)
zev_zero(float* __restrict__ zev) {
    float4 z = {0.f, 0.f, 0.f, 0.f};
    float4* p = (float4*)zev;
    unsigned g = blockIdx.x * blockDim.x + threadIdx.x;
    unsigned stride = gridDim.x * blockDim.x;
    for (; g < ZT4; g += stride) {
        unsigned off4;
        if (g < ZA4) {
            unsigned d = g / 33600u;
            unsigned rem = g - d * 33600u;
            unsigned i = rem / 210u;
            unsigned q = rem - i * 210u;
            off4 = d * 250000u + i * 250u + 40u + q;
        } else {
            unsigned h = g - ZA4;
            unsigned d = h / 210000u;
            unsigned rem = h - d * 210000u;
            unsigned i2 = rem / 250u;
            unsigned q = rem - i2 * 250u;
            off4 = d * 250000u + (160u + i2) * 250u + q;
        }
        p[off4] = z;
    }
}

// ---------------------------------------------------------------------------
// prep_k (verbatim, proven)
// ---------------------------------------------------------------------------
__global__ void prep_k(const float* __restrict__ adj,
                       const float* __restrict__ wm, const float* __restrict__ Wbeta,
                       const void* ep, const void* eps) {
    int t = threadIdx.x, lane = t & 31, wid = t >> 5;
    if (blockIdx.x < 250) {
        int row = blockIdx.x * 4 + wid;
        const float* r = adj + (size_t)row * NW;
        int cnt = 0;
        for (int base = 0; base < NW; base += 32) {
            int c = base + lane;
            float v = (c < NW) ? r[c] : 0.f;
            unsigned m = __ballot_sync(0xffffffffu, v != 0.f);
            while (m) {
                int b = __ffs(m) - 1;
                m &= m - 1;
                float vb = __shfl_sync(0xffffffffu, v, b);
                if (lane == 0 && cnt < CSR_CAP) {
                    g_ccol[row * CSR_CAP + cnt] = base + b;
                    g_cval[row * CSR_CAP + cnt] = vb;
                }
                ++cnt;
            }
        }
        if (lane == 0) g_ccnt[row] = min(cnt, CSR_CAP);
    } else if (t < NF) {
        float e1 = load_scalar(ep), e2 = load_scalar(eps);
        int j = (int)rintf((e1 / e2) * 0.3f * (float)NF);
        float wi = wm[t];
        int rank = 0;
        for (int l = 0; l < NF; ++l) {
            float wl = wm[l];
            if (wl < wi || (wl == wi && l < t)) ++rank;
        }
        g_wp[t] = (rank >= j) ? Wbeta[t] : 0.f;
    }
}

// ---------------------------------------------------------------------------
// gemm_k (verbatim, proven): T1 = bows @ W_g1
// ---------------------------------------------------------------------------
__global__ void __launch_bounds__(128)
gemm_k(const float* __restrict__ A, const float* __restrict__ B,
       const float* __restrict__ bias, float* __restrict__ C, int flags) {
    __shared__ __align__(16) float sB[NF * NF];
    __shared__ __align__(16) float sA[8 * NF];
    __shared__ float sbias[NF];
    int t = threadIdx.x, lane = t & 31, w = t >> 5;
    int r0 = blockIdx.x * 8;

    for (int i = t; i < NF * NF / 4; i += 128)
        ((float4*)sB)[i] = ((const float4*)B)[i];
    for (int i = t; i < 8 * NF / 4; i += 128)
        ((float4*)sA)[i] = ((const float4*)(A + (size_t)r0 * NF))[i];
    if (t < NF) sbias[t] = bias ? bias[t] : 0.f;
    __syncthreads();

    float acc[2][4] = {};
#pragma unroll 4
    for (int k = 0; k < NF; ++k) {
        float b0 = sB[k * NF + lane];
        float b1 = sB[k * NF + lane + 32];
        float b2 = sB[k * NF + lane + 64];
        float b3 = (lane < 4) ? sB[k * NF + lane + 96] : 0.f;
#pragma unroll
        for (int rr = 0; rr < 2; ++rr) {
            float a = sA[(w * 2 + rr) * NF + k];
            acc[rr][0] = fmaf(a, b0, acc[rr][0]);
            acc[rr][1] = fmaf(a, b1, acc[rr][1]);
            acc[rr][2] = fmaf(a, b2, acc[rr][2]);
            acc[rr][3] = fmaf(a, b3, acc[rr][3]);
        }
    }
    float bb0 = sbias[lane], bb1 = sbias[lane + 32], bb2 = sbias[lane + 64];
    float bb3 = (lane < 4) ? sbias[lane + 96] : 0.f;
#pragma unroll
    for (int rr = 0; rr < 2; ++rr) {
        acc[rr][0] += bb0; acc[rr][1] += bb1; acc[rr][2] += bb2; acc[rr][3] += bb3;
        if (flags & 1) {
            acc[rr][0] = fmaxf(acc[rr][0], 0.f);
            acc[rr][1] = fmaxf(acc[rr][1], 0.f);
            acc[rr][2] = fmaxf(acc[rr][2], 0.f);
            acc[rr][3] = fmaxf(acc[rr][3], 0.f);
        }
        float* Cr = C + (size_t)(r0 + w * 2 + rr) * NF;
        Cr[lane] = acc[rr][0];
        Cr[lane + 32] = acc[rr][1];
        Cr[lane + 64] = acc[rr][2];
        if (lane < 4) Cr[lane + 96] = acc[rr][3];
    }
}

// ---------------------------------------------------------------------------
// rowfuse1: 8 rows/block (125 blocks). H1=relu(spmm(T1)); T2 = H1 @ Wg2.
// Wg2 staged once in smem; CSR via shfl.
// ---------------------------------------------------------------------------
__global__ void __launch_bounds__(128)
rowfuse1(const float* __restrict__ T1, const float* __restrict__ Wg2,
         float* __restrict__ T2) {
    __shared__ __align__(16) float sW[NF * NF];
    __shared__ float sH1[8][NF];
    int t = threadIdx.x, lane = t & 31, w = t >> 5;
    int r0 = blockIdx.x * 8;

    for (int i = t; i < NF * NF / 4; i += 128)
        ((float4*)sW)[i] = ((const float4*)Wg2)[i];

    for (int rr = 0; rr < 2; ++rr) {
        int row = r0 + w * 2 + rr;
        float a0, a1, a2, a3;
        spmm_row_regs(T1, row, lane, a0, a1, a2, a3);
        float* Hr = sH1[w * 2 + rr];
        Hr[lane] = fmaxf(a0, 0.f);
        Hr[lane + 32] = fmaxf(a1, 0.f);
        Hr[lane + 64] = fmaxf(a2, 0.f);
        if (lane < 4) Hr[lane + 96] = fmaxf(a3, 0.f);
    }
    __syncthreads();

    float acc[2][4] = {};
#pragma unroll 4
    for (int k = 0; k < NF; ++k) {
        float b0 = sW[k * NF + lane];
        float b1 = sW[k * NF + lane + 32];
        float b2 = sW[k * NF + lane + 64];
        float b3 = (lane < 4) ? sW[k * NF + lane + 96] : 0.f;
#pragma unroll
        for (int rr = 0; rr < 2; ++rr) {
            float a = sH1[w * 2 + rr][k];
            acc[rr][0] = fmaf(a, b0, acc[rr][0]);
            acc[rr][1] = fmaf(a, b1, acc[rr][1]);
            acc[rr][2] = fmaf(a, b2, acc[rr][2]);
            acc[rr][3] = fmaf(a, b3, acc[rr][3]);
        }
    }
#pragma unroll
    for (int rr = 0; rr < 2; ++rr) {
        float* Cr = T2 + (size_t)(r0 + w * 2 + rr) * NF;
        Cr[lane] = acc[rr][0];
        Cr[lane + 32] = acc[rr][1];
        Cr[lane + 64] = acc[rr][2];
        if (lane < 4) Cr[lane + 96] = acc[rr][3];
    }
}

// ---------------------------------------------------------------------------
// rowfuse2: 8 rows/block (125 blocks).
// H = spmm(T2) -> oH ; y = H.wp ; E1 = relu(H Wh1 + b1) ;
// heli = l2norm(relu(E1 Wh2 + b2)). Wh1 then Wh2 staged through same smem.
// ---------------------------------------------------------------------------
__global__ void __launch_bounds__(128)
rowfuse2(const float* __restrict__ T2,
         const float* __restrict__ Wh1, const float* __restrict__ bh1,
         const float* __restrict__ Wh2, const float* __restrict__ bh2,
         float* __restrict__ oH, float* __restrict__ heli) {
    __shared__ __align__(16) float sW[NF * NF];
    __shared__ float sA[8][NF];
    __shared__ float sE[8][NF];
    __shared__ float sb[NF];
    int t = threadIdx.x, lane = t & 31, w = t >> 5;
    int r0 = blockIdx.x * 8;

    // stage Wh1 + bias
    for (int i = t; i < NF * NF / 4; i += 128)
        ((float4*)sW)[i] = ((const float4*)Wh1)[i];
    if (t < NF) sb[t] = bh1[t];

    // spmm rows -> sA + oH ; y dots
    for (int rr = 0; rr < 2; ++rr) {
        int row = r0 + w * 2 + rr;
        float a0, a1, a2, a3;
        spmm_row_regs(T2, row, lane, a0, a1, a2, a3);
        float* Ar = sA[w * 2 + rr];
        Ar[lane] = a0; Ar[lane + 32] = a1; Ar[lane + 64] = a2;
        if (lane < 4) Ar[lane + 96] = a3;
        float* Hr = oH + (size_t)row * NF;
        Hr[lane] = a0; Hr[lane + 32] = a1; Hr[lane + 64] = a2;
        if (lane < 4) Hr[lane + 96] = a3;
        float p = a0 * g_wp[lane] + a1 * g_wp[lane + 32] + a2 * g_wp[lane + 64];
        if (lane < 4) p = fmaf(a3, g_wp[lane + 96], p);
        p = warp_sum(p);
        if (lane == 0) g_y[row] = p;
    }
    __syncthreads();

    // E1 = relu(sA @ Wh1 + b1) -> sE
    {
        float acc[2][4];
        float bb0 = sb[lane], bb1 = sb[lane + 32], bb2 = sb[lane + 64];
        float bb3 = (lane < 4) ? sb[lane + 96] : 0.f;
#pragma unroll
        for (int rr = 0; rr < 2; ++rr) {
            acc[rr][0] = bb0; acc[rr][1] = bb1; acc[rr][2] = bb2; acc[rr][3] = bb3;
        }
#pragma unroll 4
        for (int k = 0; k < NF; ++k) {
            float b0 = sW[k * NF + lane];
            float b1 = sW[k * NF + lane + 32];
            float b2 = sW[k * NF + lane + 64];
            float b3 = (lane < 4) ? sW[k * NF + lane + 96] : 0.f;
#pragma unroll
            for (int rr = 0; rr < 2; ++rr) {
                float a = sA[w * 2 + rr][k];
                acc[rr][0] = fmaf(a, b0, acc[rr][0]);
                acc[rr][1] = fmaf(a, b1, acc[rr][1]);
                acc[rr][2] = fmaf(a, b2, acc[rr][2]);
                acc[rr][3] = fmaf(a, b3, acc[rr][3]);
            }
        }
#pragma unroll
        for (int rr = 0; rr < 2; ++rr) {
            float* Er = sE[w * 2 + rr];
            Er[lane] = fmaxf(acc[rr][0], 0.f);
            Er[lane + 32] = fmaxf(acc[rr][1], 0.f);
            Er[lane + 64] = fmaxf(acc[rr][2], 0.f);
            if (lane < 4) Er[lane + 96] = fmaxf(acc[rr][3], 0.f);
        }
    }
    __syncthreads();

    // restage Wh2 + bias
    for (int i = t; i < NF * NF / 4; i += 128)
        ((float4*)sW)[i] = ((const float4*)Wh2)[i];
    if (t < NF) sb[t] = bh2[t];
    __syncthreads();

    // heli = l2norm(relu(sE @ Wh2 + b2))
    {
        float acc[2][4];
        float bb0 = sb[lane], bb1 = sb[lane + 32], bb2 = sb[lane + 64];
        float bb3 = (lane < 4) ? sb[lane + 96] : 0.f;
#pragma unroll
        for (int rr = 0; rr < 2; ++rr) {
            acc[rr][0] = bb0; acc[rr][1] = bb1; acc[rr][2] = bb2; acc[rr][3] = bb3;
        }
#pragma unroll 4
        for (int k = 0; k < NF; ++k) {
            float b0 = sW[k * NF + lane];
            float b1 = sW[k * NF + lane + 32];
            float b2 = sW[k * NF + lane + 64];
            float b3 = (lane < 4) ? sW[k * NF + lane + 96] : 0.f;
#pragma unroll
            for (int rr = 0; rr < 2; ++rr) {
                float a = sE[w * 2 + rr][k];
                acc[rr][0] = fmaf(a, b0, acc[rr][0]);
                acc[rr][1] = fmaf(a, b1, acc[rr][1]);
                acc[rr][2] = fmaf(a, b2, acc[rr][2]);
                acc[rr][3] = fmaf(a, b3, acc[rr][3]);
            }
        }
#pragma unroll
        for (int rr = 0; rr < 2; ++rr) {
            acc[rr][0] = fmaxf(acc[rr][0], 0.f);
            acc[rr][1] = fmaxf(acc[rr][1], 0.f);
            acc[rr][2] = fmaxf(acc[rr][2], 0.f);
            acc[rr][3] = fmaxf(acc[rr][3], 0.f);
            float ss = acc[rr][0] * acc[rr][0] + acc[rr][1] * acc[rr][1]
                     + acc[rr][2] * acc[rr][2] + acc[rr][3] * acc[rr][3];
            ss = warp_sum(ss);
            float inv = 1.f / fmaxf(sqrtf(ss), 1e-12f);
            float* Cr = heli + (size_t)(r0 + w * 2 + rr) * NF;
            Cr[lane] = acc[rr][0] * inv;
            Cr[lane + 32] = acc[rr][1] * inv;
            Cr[lane + 64] = acc[rr][2] * inv;
            if (lane < 4) Cr[lane + 96] = acc[rr][3] * inv;
        }
    }
}

// ---------------------------------------------------------------------------
// beta_norm (verbatim, proven)
// ---------------------------------------------------------------------------
__global__ void __launch_bounds__(1024)
beta_norm(float* __restrict__ oBeta) {
    __shared__ float red[1024];
    int t = threadIdx.x;
    float y = (t < NW) ? g_y[t] : 0.f;
    red[t] = y * y;
    __syncthreads();
    for (int s = 512; s; s >>= 1) {
        if (t < s) red[t] += red[t + s];
        __syncthreads();
    }
    float inv = 1.f / fmaxf(sqrtf(red[0]), 1e-12f);
    if (t < NW) oBeta[t] = y * inv;
}

// ---------------------------------------------------------------------------
// gemm_nt_relu (round-2 VERBATIM — protected)
// ---------------------------------------------------------------------------
__global__ void gemm_nt_relu(const float* __restrict__ A, float* __restrict__ C,
                             int M, int K) {
    __shared__ float sA[64][21];
    __shared__ float sB[64][21];
    int tx = threadIdx.x, ty = threadIdx.y;
    int tid = ty * 16 + tx;
    int ib = blockIdx.y * 64, jb = blockIdx.x * 64;
    float acc[4][4] = {};
    for (int k0 = 0; k0 < K; k0 += 20) {
        for (int l = tid; l < 64 * 20; l += 256) {
            int r = l / 20, c = l - r * 20;
            int kk = k0 + c;
            sA[r][c] = (ib + r < M && kk < K) ? A[(size_t)(ib + r) * K + kk] : 0.f;
            sB[r][c] = (jb + r < M && kk < K) ? A[(size_t)(jb + r) * K + kk] : 0.f;
        }
        __syncthreads();
#pragma unroll
        for (int kk = 0; kk < 20; ++kk) {
            float a[4], b[4];
#pragma unroll
            for (int r = 0; r < 4; ++r) a[r] = sA[ty * 4 + r][kk];
#pragma unroll
            for (int c = 0; c < 4; ++c) b[c] = sB[tx * 4 + c][kk];
#pragma unroll
            for (int r = 0; r < 4; ++r)
#pragma unroll
                for (int c = 0; c < 4; ++c) acc[r][c] = fmaf(a[r], b[c], acc[r][c]);
        }
        __syncthreads();
    }
#pragma unroll
    for (int r = 0; r < 4; ++r) {
        int i = ib + ty * 4 + r;
        if (i >= M) continue;
#pragma unroll
        for (int c = 0; c < 4; ++c) {
            int j = jb + tx * 4 + c;
            if (j >= M) continue;
            C[(size_t)i * M + j] = fmaxf(acc[r][c], 0.f);
        }
    }
}

// ---------------------------------------------------------------------------
// doc_k (verbatim, proven)
// ---------------------------------------------------------------------------
__global__ void __launch_bounds__(512)
doc_k(const float* __restrict__ masks, const float* __restrict__ H,
      const float* __restrict__ heli, const float* __restrict__ beta_,
      const float* __restrict__ W_mu2, const float* __restrict__ b_mu2,
      const float* __restrict__ W_eta2, const float* __restrict__ b_eta2,
      const float* __restrict__ W_gm2, const float* __restrict__ b_gm2,
      const float* __restrict__ img, const float* __restrict__ W_m1,
      const float* __restrict__ b_m1, const float* __restrict__ W_m2,
      const float* __restrict__ b_m2,
      float* __restrict__ oLam, float* __restrict__ oEta,
      float* __restrict__ oGamma) {
    __shared__ int   cols[KMAX];
    __shared__ float red[512];
    __shared__ float hp[128];
    __shared__ float simg[TIw];
    __shared__ float sres[8];
    __shared__ int s_cnt;

    int d = blockIdx.x, t = threadIdx.x, lane = t & 31, wid = t >> 5;

    if (wid == 0) {
        const float* mrow = masks + (size_t)d * NW;
        int cnt = 0;
        for (int base = 0; base < NW; base += 32) {
            int c = base + lane;
            float v = (c < NW) ? mrow[c] : 0.f;
            unsigned m = __ballot_sync(0xffffffffu, v != 0.f);
            while (m) {
                int b = __ffs(m) - 1;
                m &= m - 1;
                if (lane == 0 && cnt < KMAX) cols[cnt] = base + b;
                ++cnt;
            }
        }
        if (lane == 0) s_cnt = min(cnt, KMAX);
    }
    __syncthreads();
    int cnt = s_cnt;
    float fk = (float)cnt;

    float sv = 0.f;
    if (t < NF) {
        float hpv = 0.f;
#pragma unroll 4
        for (int q = 0; q < cnt; ++q) {
            int c = cols[q];
            hpv += H[(size_t)c * NF + t];
            sv += heli[(size_t)c * NF + t];
        }
        hp[t] = hpv / fmaxf(fk, 1.f);
    }
    red[t] = (t < NF) ? sv * sv : 0.f;
    __syncthreads();
    for (int s = 256; s; s >>= 1) { if (t < s) red[t] += red[t + s]; __syncthreads(); }
    if (t == 0) sres[0] = red[0];
    __syncthreads();

    red[t] = (t < cnt) ? beta_[cols[t]] : 0.f;
    __syncthreads();
    for (int s = 256; s; s >>= 1) { if (t < s) red[t] += red[t + s]; __syncthreads(); }
    if (t == 0) sres[1] = red[0];
    __syncthreads();

    float hpt = (t < NF) ? hp[t] : 0.f;
    red[t] = (t < NF) ? hpt * W_mu2[t] : 0.f;
    __syncthreads();
    for (int s = 256; s; s >>= 1) { if (t < s) red[t] += red[t + s]; __syncthreads(); }
    if (t == 0) sres[2] = fmaxf(red[0] + b_mu2[0], 0.f);
    __syncthreads();
    red[t] = (t < NF) ? hpt * W_eta2[t] : 0.f;
    __syncthreads();
    for (int s = 256; s; s >>= 1) { if (t < s) red[t] += red[t + s]; __syncthreads(); }
    if (t == 0) sres[3] = fmaxf(red[0] + b_eta2[0], 0.f);
    __syncthreads();
    red[t] = (t < NF) ? hpt * W_gm2[t] : 0.f;
    __syncthreads();
    for (int s = 256; s; s >>= 1) { if (t < s) red[t] += red[t + s]; __syncthreads(); }
    if (t == 0) sres[4] = fmaxf(red[0] + b_gm2[0], 0.f);
    __syncthreads();

    for (int k = t; k < TIw; k += 512) simg[k] = img[(size_t)d * TIw + k];
    __syncthreads();
    float contrib = 0.f;
    if (t < HDw) {
        float h0 = b_m1[t], h1 = 0.f, h2 = 0.f, h3 = 0.f;
#pragma unroll 4
        for (int k = 0; k < TIw; k += 4) {
            h0 = fmaf(simg[k],     W_m1[(size_t)k * HDw + t],       h0);
            h1 = fmaf(simg[k + 1], W_m1[(size_t)(k + 1) * HDw + t], h1);
            h2 = fmaf(simg[k + 2], W_m1[(size_t)(k + 2) * HDw + t], h2);
            h3 = fmaf(simg[k + 3], W_m1[(size_t)(k + 3) * HDw + t], h3);
        }
        contrib = fmaxf((h0 + h1) + (h2 + h3), 0.f) * W_m2[t];
    }
    red[t] = contrib;
    __syncthreads();
    for (int s = 256; s; s >>= 1) { if (t < s) red[t] += red[t + s]; __syncthreads(); }

    if (t == 0) {
        float li = red[0] + b_m2[0];
        float Z = fmaxf(0.5f * (sres[0] - fk), 0.f);
        float inner = sres[2] + sres[1] + sres[3] * expf(-sres[4] * Z);
        float lt = 1.f / (1.f + expf(-inner));
        oLam[d] = 1.f / (1.f + expf(-(lt + li)));
        oEta[d] = sres[3];
        oGamma[d] = sres[4];
        g_kci[d] = cnt;
    }
}

// ---------------------------------------------------------------------------
// zev_patch (verbatim, proven)
// ---------------------------------------------------------------------------
__global__ void __launch_bounds__(256)
zev_patch(const float* __restrict__ oZ, float* __restrict__ zev) {
    unsigned g = blockIdx.x * 256u + threadIdx.x;
    if (g >= 640000u) return;
    unsigned d = g / 6400u;
    unsigned rem = g - d * 6400u;
    unsigned i = rem / 40u;
    unsigned q = rem - i * 40u;
    unsigned j0 = q << 2;
    int kd = g_kci[d];
    float4 v = {0.f, 0.f, 0.f, 0.f};
    if ((int)i < kd) {
        const float* zr = oZ + (size_t)i * NW + j0;
        float* vv = (float*)&v;
#pragma unroll
        for (int c = 0; c < 4; ++c) {
            int j = (int)j0 + c;
            if (j < kd && j != (int)i) {
                float tt = 2.f - 2.f * zr[c];
                vv[c] = expf(-tt * tt);
            }
        }
    }
    *(float4*)(zev + (size_t)d * NW * NW + (size_t)i * NW + j0) = v;
}

// ---------------------------------------------------------------------------
// Host launch — r12 schedule (fill at t=0, 296 blocks), depth-6 DAG
// ---------------------------------------------------------------------------
extern "C" void kernel_launch(void* const* d_in, const int* in_sizes, int n_in,
                              void* d_out, int out_size) {
    (void)in_sizes; (void)n_in; (void)out_size;
    const void*  epoch  = d_in[0];
    const void*  epochs = d_in[1];
    const float* adj    = (const float*)d_in[2];
    const float* masks  = (const float*)d_in[3];
    const float* bows   = (const float*)d_in[4];
    const float* img    = (const float*)d_in[5];
    const float* W_g1   = (const float*)d_in[6];
    const float* W_g2   = (const float*)d_in[7];
    const float* W_h1   = (const float*)d_in[8];
    const float* b_h1   = (const float*)d_in[9];
    const float* W_h2   = (const float*)d_in[10];
    const float* b_h2   = (const float*)d_in[11];
    const float* W_mu2  = (const float*)d_in[12];
    const float* b_mu2  = (const float*)d_in[13];
    const float* W_eta2 = (const float*)d_in[14];
    const float* b_eta2 = (const float*)d_in[15];
    const float* W_gm2  = (const float*)d_in[16];
    const float* b_gm2  = (const float*)d_in[17];
    const float* w_m    = (const float*)d_in[18];
    const float* W_beta = (const float*)d_in[19];
    const float* W_m1   = (const float*)d_in[20];
    const float* b_m1   = (const float*)d_in[21];
    const float* W_m2   = (const float*)d_in[22];
    const float* b_m2   = (const float*)d_in[23];

    float* out = (float*)d_out;
    float* oLam   = out + OFF_LAM;
    float* oZ     = out + OFF_ZMAT;
    float* oBeta  = out + OFF_BETA;
    float* oGamma = out + OFF_GAMMA;
    float* oEta   = out + OFF_ETA;
    float* oZev   = out + OFF_ZEV;
    float* oH     = out + OFF_H;

    float *pT1, *pT2, *pHeli;
    cudaGetSymbolAddress((void**)&pT1, g_T1);
    cudaGetSymbolAddress((void**)&pT2, g_T2);
    cudaGetSymbolAddress((void**)&pHeli, g_heli);

    // fork from capture stream
    cudaEventRecord(g_sr.fork, 0);

    // side: Z_event zero region (independent, from t=0)
    cudaStreamWaitEvent(g_sr.s_side, g_sr.fork, 0);
    zev_zero<<<296, 256, 0, g_sr.s_side>>>(oZev);
    cudaEventRecord(g_sr.ev_z, g_sr.s_side);

    // s_b: T1 = bows @ W_g1
    cudaStreamWaitEvent(g_sr.s_b, g_sr.fork, 0);
    gemm_k<<<125, 128, 0, g_sr.s_b>>>(bows, W_g1, nullptr, pT1, 0);
    cudaEventRecord(g_sr.ev_t1, g_sr.s_b);

    // s_a: prep
    cudaStreamWaitEvent(g_sr.s_a, g_sr.fork, 0);
    prep_k<<<251, 128, 0, g_sr.s_a>>>(adj, w_m, W_beta, epoch, epochs);

    // depth 2-3: rowfuse (8 rows/block, smem-staged weights)
    cudaStreamWaitEvent(g_sr.s_a, g_sr.ev_t1, 0);
    rowfuse1<<<125, 128, 0, g_sr.s_a>>>(pT1, W_g2, pT2);
    rowfuse2<<<125, 128, 0, g_sr.s_a>>>(pT2, W_h1, b_h1, W_h2, b_h2, oH, pHeli);
    cudaEventRecord(g_sr.ev3, g_sr.s_a);

    // depth 4 (parallel): beta on s_b ; zgemm on s_a
    cudaStreamWaitEvent(g_sr.s_b, g_sr.ev3, 0);
    beta_norm<<<1, 1024, 0, g_sr.s_b>>>(oBeta);
    cudaEventRecord(g_sr.ev_beta, g_sr.s_b);

    {
        dim3 grid((NW + 63) / 64, (NW + 63) / 64);
        dim3 block(16, 16);
        gemm_nt_relu<<<grid, block, 0, g_sr.s_a>>>(pHeli, oZ, NW, NF);
    }

    // depth 5: doc
    cudaStreamWaitEvent(g_sr.s_a, g_sr.ev_beta, 0);
    doc_k<<<ND, 512, 0, g_sr.s_a>>>(masks, oH, pHeli, oBeta,
                                    W_mu2, b_mu2, W_eta2, b_eta2, W_gm2, b_gm2,
                                    img, W_m1, b_m1, W_m2, b_m2,
                                    oLam, oEta, oGamma);

    // depth 6: patch
    cudaStreamWaitEvent(g_sr.s_a, g_sr.ev_z, 0);
    zev_patch<<<2500, 256, 0, g_sr.s_a>>>(oZ, oZev);
    cudaEventRecord(g_sr.ev_final, g_sr.s_a);

    // join back to the capture stream
    cudaStreamWaitEvent(0, g_sr.ev_final, 0);
}

// round 15
// speedup vs baseline: 1.0606x; 1.0606x over previous
#include <cuda_runtime.h>
#include <cuda_bf16.h>
#include <math.h>
#include <stdint.h>

// ---------------------------------------------------------------------------
// Problem constants
// ---------------------------------------------------------------------------
#define NW 1000
#define ND 100
#define NF 100
#define TIw 512
#define HDw 128

// Output layout (concatenated f32)
#define OFF_LAM   0
#define OFF_ZMAT  100
#define OFF_BETA  1000100
#define OFF_GAMMA 1001100
#define OFF_ETA   1001200
#define OFF_ZEV   1001300
#define OFF_H     101001300

#define KMAX 160

// ---------------------------------------------------------------------------
// Device scratch
// ---------------------------------------------------------------------------
__device__ __align__(16) float g_T1[NW * NF];
__device__ __align__(16) float g_T2[NW * NF];
__device__ __align__(16) float g_heli[NW * NF];
__device__ float g_y[NW];
__device__ float g_wp[NF];
__device__ int   g_kci[ND];

#define CSR_CAP 96
__device__ int   g_ccnt[NW];
__device__ int   g_ccol[NW * CSR_CAP];
__device__ float g_cval[NW * CSR_CAP];

__device__ __forceinline__ float warp_sum(float v) {
#pragma unroll
    for (int o = 16; o; o >>= 1) v += __shfl_xor_sync(0xffffffffu, v, o);
    return v;
}

__device__ __forceinline__ float load_scalar(const void* p) {
    int v = *(const int*)p;
    if (v >= 0 && v <= 1000000) return (float)v;
    return *(const float*)p;
}

// SpMM one row via CSR with shfl-broadcast (r10/r14 proven). Results in regs.
__device__ __forceinline__ void spmm_row_regs(const float* __restrict__ X,
                                              int row, int lane,
                                              float& a0, float& a1,
                                              float& a2, float& a3) {
    int nnz = g_ccnt[row];
    const int* cols = g_ccol + row * CSR_CAP;
    const float* vals = g_cval + row * CSR_CAP;
    int   c0 = (lane < nnz) ? cols[lane] : 0;
    float v0 = (lane < nnz) ? vals[lane] : 0.f;
    int   c1 = (lane + 32 < nnz) ? cols[lane + 32] : 0;
    float v1 = (lane + 32 < nnz) ? vals[lane + 32] : 0.f;
    int   c2 = (lane + 64 < nnz) ? cols[lane + 64] : 0;
    float v2 = (lane + 64 < nnz) ? vals[lane + 64] : 0.f;

    a0 = 0.f; a1 = 0.f; a2 = 0.f; a3 = 0.f;
    int lim0 = min(32, nnz);
    for (int s = 0; s < lim0; ++s) {
        int cc = __shfl_sync(0xffffffffu, c0, s);
        float vv = __shfl_sync(0xffffffffu, v0, s);
        const float* Xr = X + (size_t)cc * NF;
        a0 = fmaf(vv, Xr[lane], a0);
        a1 = fmaf(vv, Xr[lane + 32], a1);
        a2 = fmaf(vv, Xr[lane + 64], a2);
        if (lane < 4) a3 = fmaf(vv, Xr[lane + 96], a3);
    }
    if (nnz > 32) {
        int lim1 = min(32, nnz - 32);
        for (int s = 0; s < lim1; ++s) {
            int cc = __shfl_sync(0xffffffffu, c1, s);
            float vv = __shfl_sync(0xffffffffu, v1, s);
            const float* Xr = X + (size_t)cc * NF;
            a0 = fmaf(vv, Xr[lane], a0);
            a1 = fmaf(vv, Xr[lane + 32], a1);
            a2 = fmaf(vv, Xr[lane + 64], a2);
            if (lane < 4) a3 = fmaf(vv, Xr[lane + 96], a3);
        }
    }
    if (nnz > 64) {
        int lim2 = min(32, nnz - 64);
        for (int s = 0; s < lim2; ++s) {
            int cc = __shfl_sync(0xffffffffu, c2, s);
            float vv = __shfl_sync(0xffffffffu, v2, s);
            const float* Xr = X + (size_t)cc * NF;
            a0 = fmaf(vv, Xr[lane], a0);
            a1 = fmaf(vv, Xr[lane + 32], a1);
            a2 = fmaf(vv, Xr[lane + 64], a2);
            if (lane < 4) a3 = fmaf(vv, Xr[lane + 96], a3);
        }
    }
}

// ---------------------------------------------------------------------------
// Streams + events (static init; not during capture)
// ---------------------------------------------------------------------------
struct SideRes {
    cudaStream_t s_side, s_a, s_b;
    cudaEvent_t fork, ev_z, ev_t1, ev3, ev_beta, ev_zg, ev_final;
    SideRes() {
        int lo = 0, hi = 0;
        cudaDeviceGetStreamPriorityRange(&lo, &hi);
        cudaStreamCreateWithPriority(&s_side, cudaStreamNonBlocking, lo);
        cudaStreamCreateWithFlags(&s_a, cudaStreamNonBlocking);
        cudaStreamCreateWithFlags(&s_b, cudaStreamNonBlocking);
        cudaEventCreateWithFlags(&fork, cudaEventDisableTiming);
        cudaEventCreateWithFlags(&ev_z, cudaEventDisableTiming);
        cudaEventCreateWithFlags(&ev_t1, cudaEventDisableTiming);
        cudaEventCreateWithFlags(&ev3, cudaEventDisableTiming);
        cudaEventCreateWithFlags(&ev_beta, cudaEventDisableTiming);
        cudaEventCreateWithFlags(&ev_zg, cudaEventDisableTiming);
        cudaEventCreateWithFlags(&ev_final, cudaEventDisableTiming);
    }
};
static SideRes g_sr;

// ---------------------------------------------------------------------------
// zev_zero — proven shape (296 blk = 67.8us @ 61.8% DRAM). Deferred to ev3.
// ---------------------------------------------------------------------------
#define ZA4 (100u * 160u * 210u)
#define ZB4 (100u * 840u * 250u)
#define ZT4 (ZA4 + ZB4)

__global__ void __launch_bounds__(256)
zev_zero(float* __restrict__ zev) {
    float4 z = {0.f, 0.f, 0.f, 0.f};
    float4* p = (float4*)zev;
    unsigned g = blockIdx.x * blockDim.x + threadIdx.x;
    unsigned stride = gridDim.x * blockDim.x;
    for (; g < ZT4; g += stride) {
        unsigned off4;
        if (g < ZA4) {
            unsigned d = g / 33600u;
            unsigned rem = g - d * 33600u;
            unsigned i = rem / 210u;
            unsigned q = rem - i * 210u;
            off4 = d * 250000u + i * 250u + 40u + q;
        } else {
            unsigned h = g - ZA4;
            unsigned d = h / 210000u;
            unsigned rem = h - d * 210000u;
            unsigned i2 = rem / 250u;
            unsigned q = rem - i2 * 250u;
            off4 = d * 250000u + (160u + i2) * 250u + q;
        }
        p[off4] = z;
    }
}

// ---------------------------------------------------------------------------
// prep_k (verbatim, proven)
// ---------------------------------------------------------------------------
__global__ void prep_k(const float* __restrict__ adj,
                       const float* __restrict__ wm, const float* __restrict__ Wbeta,
                       const void* ep, const void* eps) {
    int t = threadIdx.x, lane = t & 31, wid = t >> 5;
    if (blockIdx.x < 250) {
        int row = blockIdx.x * 4 + wid;
        const float* r = adj + (size_t)row * NW;
        int cnt = 0;
        for (int base = 0; base < NW; base += 32) {
            int c = base + lane;
            float v = (c < NW) ? r[c] : 0.f;
            unsigned m = __ballot_sync(0xffffffffu, v != 0.f);
            while (m) {
                int b = __ffs(m) - 1;
                m &= m - 1;
                float vb = __shfl_sync(0xffffffffu, v, b);
                if (lane == 0 && cnt < CSR_CAP) {
                    g_ccol[row * CSR_CAP + cnt] = base + b;
                    g_cval[row * CSR_CAP + cnt] = vb;
                }
                ++cnt;
            }
        }
        if (lane == 0) g_ccnt[row] = min(cnt, CSR_CAP);
    } else if (t < NF) {
        float e1 = load_scalar(ep), e2 = load_scalar(eps);
        int j = (int)rintf((e1 / e2) * 0.3f * (float)NF);
        float wi = wm[t];
        int rank = 0;
        for (int l = 0; l < NF; ++l) {
            float wl = wm[l];
            if (wl < wi || (wl == wi && l < t)) ++rank;
        }
        g_wp[t] = (rank >= j) ? Wbeta[t] : 0.f;
    }
}

// ---------------------------------------------------------------------------
// gemm_k (verbatim, proven): T1 = bows @ W_g1
// ---------------------------------------------------------------------------
__global__ void __launch_bounds__(128)
gemm_k(const float* __restrict__ A, const float* __restrict__ B,
       const float* __restrict__ bias, float* __restrict__ C, int flags) {
    __shared__ __align__(16) float sB[NF * NF];
    __shared__ __align__(16) float sA[8 * NF];
    __shared__ float sbias[NF];
    int t = threadIdx.x, lane = t & 31, w = t >> 5;
    int r0 = blockIdx.x * 8;

    for (int i = t; i < NF * NF / 4; i += 128)
        ((float4*)sB)[i] = ((const float4*)B)[i];
    for (int i = t; i < 8 * NF / 4; i += 128)
        ((float4*)sA)[i] = ((const float4*)(A + (size_t)r0 * NF))[i];
    if (t < NF) sbias[t] = bias ? bias[t] : 0.f;
    __syncthreads();

    float acc[2][4] = {};
#pragma unroll 4
    for (int k = 0; k < NF; ++k) {
        float b0 = sB[k * NF + lane];
        float b1 = sB[k * NF + lane + 32];
        float b2 = sB[k * NF + lane + 64];
        float b3 = (lane < 4) ? sB[k * NF + lane + 96] : 0.f;
#pragma unroll
        for (int rr = 0; rr < 2; ++rr) {
            float a = sA[(w * 2 + rr) * NF + k];
            acc[rr][0] = fmaf(a, b0, acc[rr][0]);
            acc[rr][1] = fmaf(a, b1, acc[rr][1]);
            acc[rr][2] = fmaf(a, b2, acc[rr][2]);
            acc[rr][3] = fmaf(a, b3, acc[rr][3]);
        }
    }
    float bb0 = sbias[lane], bb1 = sbias[lane + 32], bb2 = sbias[lane + 64];
    float bb3 = (lane < 4) ? sbias[lane + 96] : 0.f;
#pragma unroll
    for (int rr = 0; rr < 2; ++rr) {
        acc[rr][0] += bb0; acc[rr][1] += bb1; acc[rr][2] += bb2; acc[rr][3] += bb3;
        if (flags & 1) {
            acc[rr][0] = fmaxf(acc[rr][0], 0.f);
            acc[rr][1] = fmaxf(acc[rr][1], 0.f);
            acc[rr][2] = fmaxf(acc[rr][2], 0.f);
            acc[rr][3] = fmaxf(acc[rr][3], 0.f);
        }
        float* Cr = C + (size_t)(r0 + w * 2 + rr) * NF;
        Cr[lane] = acc[rr][0];
        Cr[lane + 32] = acc[rr][1];
        Cr[lane + 64] = acc[rr][2];
        if (lane < 4) Cr[lane + 96] = acc[rr][3];
    }
}

// ---------------------------------------------------------------------------
// rowfuse1 (r14 verbatim, smem-staged): 8 rows/block, 125 blocks.
// ---------------------------------------------------------------------------
__global__ void __launch_bounds__(128)
rowfuse1(const float* __restrict__ T1, const float* __restrict__ Wg2,
         float* __restrict__ T2) {
    __shared__ __align__(16) float sW[NF * NF];
    __shared__ float sH1[8][NF];
    int t = threadIdx.x, lane = t & 31, w = t >> 5;
    int r0 = blockIdx.x * 8;

    for (int i = t; i < NF * NF / 4; i += 128)
        ((float4*)sW)[i] = ((const float4*)Wg2)[i];

    for (int rr = 0; rr < 2; ++rr) {
        int row = r0 + w * 2 + rr;
        float a0, a1, a2, a3;
        spmm_row_regs(T1, row, lane, a0, a1, a2, a3);
        float* Hr = sH1[w * 2 + rr];
        Hr[lane] = fmaxf(a0, 0.f);
        Hr[lane + 32] = fmaxf(a1, 0.f);
        Hr[lane + 64] = fmaxf(a2, 0.f);
        if (lane < 4) Hr[lane + 96] = fmaxf(a3, 0.f);
    }
    __syncthreads();

    float acc[2][4] = {};
#pragma unroll 4
    for (int k = 0; k < NF; ++k) {
        float b0 = sW[k * NF + lane];
        float b1 = sW[k * NF + lane + 32];
        float b2 = sW[k * NF + lane + 64];
        float b3 = (lane < 4) ? sW[k * NF + lane + 96] : 0.f;
#pragma unroll
        for (int rr = 0; rr < 2; ++rr) {
            float a = sH1[w * 2 + rr][k];
            acc[rr][0] = fmaf(a, b0, acc[rr][0]);
            acc[rr][1] = fmaf(a, b1, acc[rr][1]);
            acc[rr][2] = fmaf(a, b2, acc[rr][2]);
            acc[rr][3] = fmaf(a, b3, acc[rr][3]);
        }
    }
#pragma unroll
    for (int rr = 0; rr < 2; ++rr) {
        float* Cr = T2 + (size_t)(r0 + w * 2 + rr) * NF;
        Cr[lane] = acc[rr][0];
        Cr[lane + 32] = acc[rr][1];
        Cr[lane + 64] = acc[rr][2];
        if (lane < 4) Cr[lane + 96] = acc[rr][3];
    }
}

// ---------------------------------------------------------------------------
// rowfuse2 (r14 verbatim, smem-staged): 8 rows/block, 125 blocks.
// ---------------------------------------------------------------------------
__global__ void __launch_bounds__(128)
rowfuse2(const float* __restrict__ T2,
         const float* __restrict__ Wh1, const float* __restrict__ bh1,
         const float* __restrict__ Wh2, const float* __restrict__ bh2,
         float* __restrict__ oH, float* __restrict__ heli) {
    __shared__ __align__(16) float sW[NF * NF];
    __shared__ float sA[8][NF];
    __shared__ float sE[8][NF];
    __shared__ float sb[NF];
    int t = threadIdx.x, lane = t & 31, w = t >> 5;
    int r0 = blockIdx.x * 8;

    for (int i = t; i < NF * NF / 4; i += 128)
        ((float4*)sW)[i] = ((const float4*)Wh1)[i];
    if (t < NF) sb[t] = bh1[t];

    for (int rr = 0; rr < 2; ++rr) {
        int row = r0 + w * 2 + rr;
        float a0, a1, a2, a3;
        spmm_row_regs(T2, row, lane, a0, a1, a2, a3);
        float* Ar = sA[w * 2 + rr];
        Ar[lane] = a0; Ar[lane + 32] = a1; Ar[lane + 64] = a2;
        if (lane < 4) Ar[lane + 96] = a3;
        float* Hr = oH + (size_t)row * NF;
        Hr[lane] = a0; Hr[lane + 32] = a1; Hr[lane + 64] = a2;
        if (lane < 4) Hr[lane + 96] = a3;
        float p = a0 * g_wp[lane] + a1 * g_wp[lane + 32] + a2 * g_wp[lane + 64];
        if (lane < 4) p = fmaf(a3, g_wp[lane + 96], p);
        p = warp_sum(p);
        if (lane == 0) g_y[row] = p;
    }
    __syncthreads();

    {
        float acc[2][4];
        float bb0 = sb[lane], bb1 = sb[lane + 32], bb2 = sb[lane + 64];
        float bb3 = (lane < 4) ? sb[lane + 96] : 0.f;
#pragma unroll
        for (int rr = 0; rr < 2; ++rr) {
            acc[rr][0] = bb0; acc[rr][1] = bb1; acc[rr][2] = bb2; acc[rr][3] = bb3;
        }
#pragma unroll 4
        for (int k = 0; k < NF; ++k) {
            float b0 = sW[k * NF + lane];
            float b1 = sW[k * NF + lane + 32];
            float b2 = sW[k * NF + lane + 64];
            float b3 = (lane < 4) ? sW[k * NF + lane + 96] : 0.f;
#pragma unroll
            for (int rr = 0; rr < 2; ++rr) {
                float a = sA[w * 2 + rr][k];
                acc[rr][0] = fmaf(a, b0, acc[rr][0]);
                acc[rr][1] = fmaf(a, b1, acc[rr][1]);
                acc[rr][2] = fmaf(a, b2, acc[rr][2]);
                acc[rr][3] = fmaf(a, b3, acc[rr][3]);
            }
        }
#pragma unroll
        for (int rr = 0; rr < 2; ++rr) {
            float* Er = sE[w * 2 + rr];
            Er[lane] = fmaxf(acc[rr][0], 0.f);
            Er[lane + 32] = fmaxf(acc[rr][1], 0.f);
            Er[lane + 64] = fmaxf(acc[rr][2], 0.f);
            if (lane < 4) Er[lane + 96] = fmaxf(acc[rr][3], 0.f);
        }
    }
    __syncthreads();

    for (int i = t; i < NF * NF / 4; i += 128)
        ((float4*)sW)[i] = ((const float4*)Wh2)[i];
    if (t < NF) sb[t] = bh2[t];
    __syncthreads();

    {
        float acc[2][4];
        float bb0 = sb[lane], bb1 = sb[lane + 32], bb2 = sb[lane + 64];
        float bb3 = (lane < 4) ? sb[lane + 96] : 0.f;
#pragma unroll
        for (int rr = 0; rr < 2; ++rr) {
            acc[rr][0] = bb0; acc[rr][1] = bb1; acc[rr][2] = bb2; acc[rr][3] = bb3;
        }
#pragma unroll 4
        for (int k = 0; k < NF; ++k) {
            float b0 = sW[k * NF + lane];
            float b1 = sW[k * NF + lane + 32];
            float b2 = sW[k * NF + lane + 64];
            float b3 = (lane < 4) ? sW[k * NF + lane + 96] : 0.f;
#pragma unroll
            for (int rr = 0; rr < 2; ++rr) {
                float a = sE[w * 2 + rr][k];
                acc[rr][0] = fmaf(a, b0, acc[rr][0]);
                acc[rr][1] = fmaf(a, b1, acc[rr][1]);
                acc[rr][2] = fmaf(a, b2, acc[rr][2]);
                acc[rr][3] = fmaf(a, b3, acc[rr][3]);
            }
        }
#pragma unroll
        for (int rr = 0; rr < 2; ++rr) {
            acc[rr][0] = fmaxf(acc[rr][0], 0.f);
            acc[rr][1] = fmaxf(acc[rr][1], 0.f);
            acc[rr][2] = fmaxf(acc[rr][2], 0.f);
            acc[rr][3] = fmaxf(acc[rr][3], 0.f);
            float ss = acc[rr][0] * acc[rr][0] + acc[rr][1] * acc[rr][1]
                     + acc[rr][2] * acc[rr][2] + acc[rr][3] * acc[rr][3];
            ss = warp_sum(ss);
            float inv = 1.f / fmaxf(sqrtf(ss), 1e-12f);
            float* Cr = heli + (size_t)(r0 + w * 2 + rr) * NF;
            Cr[lane] = acc[rr][0] * inv;
            Cr[lane + 32] = acc[rr][1] * inv;
            Cr[lane + 64] = acc[rr][2] * inv;
            if (lane < 4) Cr[lane + 96] = acc[rr][3] * inv;
        }
    }
}

// ---------------------------------------------------------------------------
// beta_norm (verbatim, proven)
// ---------------------------------------------------------------------------
__global__ void __launch_bounds__(1024)
beta_norm(float* __restrict__ oBeta) {
    __shared__ float red[1024];
    int t = threadIdx.x;
    float y = (t < NW) ? g_y[t] : 0.f;
    red[t] = y * y;
    __syncthreads();
    for (int s = 512; s; s >>= 1) {
        if (t < s) red[t] += red[t + s];
        __syncthreads();
    }
    float inv = 1.f / fmaxf(sqrtf(red[0]), 1e-12f);
    if (t < NW) oBeta[t] = y * inv;
}

// ---------------------------------------------------------------------------
// gemm_nt_relu (round-2 VERBATIM — protected)
// ---------------------------------------------------------------------------
__global__ void gemm_nt_relu(const float* __restrict__ A, float* __restrict__ C,
                             int M, int K) {
    __shared__ float sA[64][21];
    __shared__ float sB[64][21];
    int tx = threadIdx.x, ty = threadIdx.y;
    int tid = ty * 16 + tx;
    int ib = blockIdx.y * 64, jb = blockIdx.x * 64;
    float acc[4][4] = {};
    for (int k0 = 0; k0 < K; k0 += 20) {
        for (int l = tid; l < 64 * 20; l += 256) {
            int r = l / 20, c = l - r * 20;
            int kk = k0 + c;
            sA[r][c] = (ib + r < M && kk < K) ? A[(size_t)(ib + r) * K + kk] : 0.f;
            sB[r][c] = (jb + r < M && kk < K) ? A[(size_t)(jb + r) * K + kk] : 0.f;
        }
        __syncthreads();
#pragma unroll
        for (int kk = 0; kk < 20; ++kk) {
            float a[4], b[4];
#pragma unroll
            for (int r = 0; r < 4; ++r) a[r] = sA[ty * 4 + r][kk];
#pragma unroll
            for (int c = 0; c < 4; ++c) b[c] = sB[tx * 4 + c][kk];
#pragma unroll
            for (int r = 0; r < 4; ++r)
#pragma unroll
                for (int c = 0; c < 4; ++c) acc[r][c] = fmaf(a[r], b[c], acc[r][c]);
        }
        __syncthreads();
    }
#pragma unroll
    for (int r = 0; r < 4; ++r) {
        int i = ib + ty * 4 + r;
        if (i >= M) continue;
#pragma unroll
        for (int c = 0; c < 4; ++c) {
            int j = jb + tx * 4 + c;
            if (j >= M) continue;
            C[(size_t)i * M + j] = fmaxf(acc[r][c], 0.f);
        }
    }
}

// ---------------------------------------------------------------------------
// doc_k (verbatim, proven)
// ---------------------------------------------------------------------------
__global__ void __launch_bounds__(512)
doc_k(const float* __restrict__ masks, const float* __restrict__ H,
      const float* __restrict__ heli, const float* __restrict__ beta_,
      const float* __restrict__ W_mu2, const float* __restrict__ b_mu2,
      const float* __restrict__ W_eta2, const float* __restrict__ b_eta2,
      const float* __restrict__ W_gm2, const float* __restrict__ b_gm2,
      const float* __restrict__ img, const float* __restrict__ W_m1,
      const float* __restrict__ b_m1, const float* __restrict__ W_m2,
      const float* __restrict__ b_m2,
      float* __restrict__ oLam, float* __restrict__ oEta,
      float* __restrict__ oGamma) {
    __shared__ int   cols[KMAX];
    __shared__ float red[512];
    __shared__ float hp[128];
    __shared__ float simg[TIw];
    __shared__ float sres[8];
    __shared__ int s_cnt;

    int d = blockIdx.x, t = threadIdx.x, lane = t & 31, wid = t >> 5;

    if (wid == 0) {
        const float* mrow = masks + (size_t)d * NW;
        int cnt = 0;
        for (int base = 0; base < NW; base += 32) {
            int c = base + lane;
            float v = (c < NW) ? mrow[c] : 0.f;
            unsigned m = __ballot_sync(0xffffffffu, v != 0.f);
            while (m) {
                int b = __ffs(m) - 1;
                m &= m - 1;
                if (lane == 0 && cnt < KMAX) cols[cnt] = base + b;
                ++cnt;
            }
        }
        if (lane == 0) s_cnt = min(cnt, KMAX);
    }
    __syncthreads();
    int cnt = s_cnt;
    float fk = (float)cnt;

    float sv = 0.f;
    if (t < NF) {
        float hpv = 0.f;
#pragma unroll 4
        for (int q = 0; q < cnt; ++q) {
            int c = cols[q];
            hpv += H[(size_t)c * NF + t];
            sv += heli[(size_t)c * NF + t];
        }
        hp[t] = hpv / fmaxf(fk, 1.f);
    }
    red[t] = (t < NF) ? sv * sv : 0.f;
    __syncthreads();
    for (int s = 256; s; s >>= 1) { if (t < s) red[t] += red[t + s]; __syncthreads(); }
    if (t == 0) sres[0] = red[0];
    __syncthreads();

    red[t] = (t < cnt) ? beta_[cols[t]] : 0.f;
    __syncthreads();
    for (int s = 256; s; s >>= 1) { if (t < s) red[t] += red[t + s]; __syncthreads(); }
    if (t == 0) sres[1] = red[0];
    __syncthreads();

    float hpt = (t < NF) ? hp[t] : 0.f;
    red[t] = (t < NF) ? hpt * W_mu2[t] : 0.f;
    __syncthreads();
    for (int s = 256; s; s >>= 1) { if (t < s) red[t] += red[t + s]; __syncthreads(); }
    if (t == 0) sres[2] = fmaxf(red[0] + b_mu2[0], 0.f);
    __syncthreads();
    red[t] = (t < NF) ? hpt * W_eta2[t] : 0.f;
    __syncthreads();
    for (int s = 256; s; s >>= 1) { if (t < s) red[t] += red[t + s]; __syncthreads(); }
    if (t == 0) sres[3] = fmaxf(red[0] + b_eta2[0], 0.f);
    __syncthreads();
    red[t] = (t < NF) ? hpt * W_gm2[t] : 0.f;
    __syncthreads();
    for (int s = 256; s; s >>= 1) { if (t < s) red[t] += red[t + s]; __syncthreads(); }
    if (t == 0) sres[4] = fmaxf(red[0] + b_gm2[0], 0.f);
    __syncthreads();

    for (int k = t; k < TIw; k += 512) simg[k] = img[(size_t)d * TIw + k];
    __syncthreads();
    float contrib = 0.f;
    if (t < HDw) {
        float h0 = b_m1[t], h1 = 0.f, h2 = 0.f, h3 = 0.f;
#pragma unroll 4
        for (int k = 0; k < TIw; k += 4) {
            h0 = fmaf(simg[k],     W_m1[(size_t)k * HDw + t],       h0);
            h1 = fmaf(simg[k + 1], W_m1[(size_t)(k + 1) * HDw + t], h1);
            h2 = fmaf(simg[k + 2], W_m1[(size_t)(k + 2) * HDw + t], h2);
            h3 = fmaf(simg[k + 3], W_m1[(size_t)(k + 3) * HDw + t], h3);
        }
        contrib = fmaxf((h0 + h1) + (h2 + h3), 0.f) * W_m2[t];
    }
    red[t] = contrib;
    __syncthreads();
    for (int s = 256; s; s >>= 1) { if (t < s) red[t] += red[t + s]; __syncthreads(); }

    if (t == 0) {
        float li = red[0] + b_m2[0];
        float Z = fmaxf(0.5f * (sres[0] - fk), 0.f);
        float inner = sres[2] + sres[1] + sres[3] * expf(-sres[4] * Z);
        float lt = 1.f / (1.f + expf(-inner));
        oLam[d] = 1.f / (1.f + expf(-(lt + li)));
        oEta[d] = sres[3];
        oGamma[d] = sres[4];
        g_kci[d] = cnt;
    }
}

// ---------------------------------------------------------------------------
// zev_patch (verbatim, proven). Disjoint from zev_zero's region.
// ---------------------------------------------------------------------------
__global__ void __launch_bounds__(256)
zev_patch(const float* __restrict__ oZ, float* __restrict__ zev) {
    unsigned g = blockIdx.x * 256u + threadIdx.x;
    if (g >= 640000u) return;
    unsigned d = g / 6400u;
    unsigned rem = g - d * 6400u;
    unsigned i = rem / 40u;
    unsigned q = rem - i * 40u;
    unsigned j0 = q << 2;
    int kd = g_kci[d];
    float4 v = {0.f, 0.f, 0.f, 0.f};
    if ((int)i < kd) {
        const float* zr = oZ + (size_t)i * NW + j0;
        float* vv = (float*)&v;
#pragma unroll
        for (int c = 0; c < 4; ++c) {
            int j = (int)j0 + c;
            if (j < kd && j != (int)i) {
                float tt = 2.f - 2.f * zr[c];
                vv[c] = expf(-tt * tt);
            }
        }
    }
    *(float4*)(zev + (size_t)d * NW * NW + (size_t)i * NW + j0) = v;
}

// ---------------------------------------------------------------------------
// Host launch — uncontended prefix, fill overlaps tail only, patch ∥ fill.
// ---------------------------------------------------------------------------
extern "C" void kernel_launch(void* const* d_in, const int* in_sizes, int n_in,
                              void* d_out, int out_size) {
    (void)in_sizes; (void)n_in; (void)out_size;
    const void*  epoch  = d_in[0];
    const void*  epochs = d_in[1];
    const float* adj    = (const float*)d_in[2];
    const float* masks  = (const float*)d_in[3];
    const float* bows   = (const float*)d_in[4];
    const float* img    = (const float*)d_in[5];
    const float* W_g1   = (const float*)d_in[6];
    const float* W_g2   = (const float*)d_in[7];
    const float* W_h1   = (const float*)d_in[8];
    const float* b_h1   = (const float*)d_in[9];
    const float* W_h2   = (const float*)d_in[10];
    const float* b_h2   = (const float*)d_in[11];
    const float* W_mu2  = (const float*)d_in[12];
    const float* b_mu2  = (const float*)d_in[13];
    const float* W_eta2 = (const float*)d_in[14];
    const float* b_eta2 = (const float*)d_in[15];
    const float* W_gm2  = (const float*)d_in[16];
    const float* b_gm2  = (const float*)d_in[17];
    const float* w_m    = (const float*)d_in[18];
    const float* W_beta = (const float*)d_in[19];
    const float* W_m1   = (const float*)d_in[20];
    const float* b_m1   = (const float*)d_in[21];
    const float* W_m2   = (const float*)d_in[22];
    const float* b_m2   = (const float*)d_in[23];

    float* out = (float*)d_out;
    float* oLam   = out + OFF_LAM;
    float* oZ     = out + OFF_ZMAT;
    float* oBeta  = out + OFF_BETA;
    float* oGamma = out + OFF_GAMMA;
    float* oEta   = out + OFF_ETA;
    float* oZev   = out + OFF_ZEV;
    float* oH     = out + OFF_H;

    float *pT1, *pT2, *pHeli;
    cudaGetSymbolAddress((void**)&pT1, g_T1);
    cudaGetSymbolAddress((void**)&pT2, g_T2);
    cudaGetSymbolAddress((void**)&pHeli, g_heli);

    // fork from capture stream
    cudaEventRecord(g_sr.fork, 0);

    // ---- phase 1: uncontended prefix ----
    cudaStreamWaitEvent(g_sr.s_b, g_sr.fork, 0);
    gemm_k<<<125, 128, 0, g_sr.s_b>>>(bows, W_g1, nullptr, pT1, 0);
    cudaEventRecord(g_sr.ev_t1, g_sr.s_b);

    cudaStreamWaitEvent(g_sr.s_a, g_sr.fork, 0);
    prep_k<<<251, 128, 0, g_sr.s_a>>>(adj, w_m, W_beta, epoch, epochs);

    cudaStreamWaitEvent(g_sr.s_a, g_sr.ev_t1, 0);
    rowfuse1<<<125, 128, 0, g_sr.s_a>>>(pT1, W_g2, pT2);
    rowfuse2<<<125, 128, 0, g_sr.s_a>>>(pT2, W_h1, b_h1, W_h2, b_h2, oH, pHeli);
    cudaEventRecord(g_sr.ev3, g_sr.s_a);

    // ---- phase 2: fill starts now (side stream), overlapping the tail ----
    cudaStreamWaitEvent(g_sr.s_side, g_sr.ev3, 0);
    zev_zero<<<296, 256, 0, g_sr.s_side>>>(oZev);
    cudaEventRecord(g_sr.ev_z, g_sr.s_side);

    // tail: beta_norm + doc on s_b ; zgemm on s_a (independent of doc)
    cudaStreamWaitEvent(g_sr.s_b, g_sr.ev3, 0);
    beta_norm<<<1, 1024, 0, g_sr.s_b>>>(oBeta);
    doc_k<<<ND, 512, 0, g_sr.s_b>>>(masks, oH, pHeli, oBeta,
                                    W_mu2, b_mu2, W_eta2, b_eta2, W_gm2, b_gm2,
                                    img, W_m1, b_m1, W_m2, b_m2,
                                    oLam, oEta, oGamma);
    cudaEventRecord(g_sr.ev_beta, g_sr.s_b);

    {
        dim3 grid((NW + 63) / 64, (NW + 63) / 64);
        dim3 block(16, 16);
        gemm_nt_relu<<<grid, block, 0, g_sr.s_a>>>(pHeli, oZ, NW, NF);
    }

    // patch: needs Z_ (s_a in-order) + kci (ev_beta); DISJOINT from fill ->
    // runs concurrently with zev_zero.
    cudaStreamWaitEvent(g_sr.s_a, g_sr.ev_beta, 0);
    zev_patch<<<2500, 256, 0, g_sr.s_a>>>(oZ, oZev);
    cudaEventRecord(g_sr.ev_final, g_sr.s_a);

    // join: capture stream waits for compute chain AND the fill
    cudaStreamWaitEvent(0, g_sr.ev_final, 0);
    cudaStreamWaitEvent(0, g_sr.ev_z, 0);
}

// round 16
// speedup vs baseline: 1.1118x; 1.0483x over previous
#include <cuda_runtime.h>
#include <cuda_bf16.h>
#include <math.h>
#include <stdint.h>

// ---------------------------------------------------------------------------
// Problem constants
// ---------------------------------------------------------------------------
#define NW 1000
#define ND 100
#define NF 100
#define TIw 512
#define HDw 128

// Output layout (concatenated f32)
#define OFF_LAM   0
#define OFF_ZMAT  100
#define OFF_BETA  1000100
#define OFF_GAMMA 1001100
#define OFF_ETA   1001200
#define OFF_ZEV   1001300
#define OFF_H     101001300

#define KMAX 160

// ---------------------------------------------------------------------------
// Device scratch
// ---------------------------------------------------------------------------
__device__ __align__(16) float g_H1[NW * NF];
__device__ __align__(16) float g_heli[NW * NF];
__device__ float g_y[NW];
__device__ float g_wp[NF];
__device__ int   g_kci[ND];

#define CSR_CAP 96
__device__ int   g_ccnt[NW];
__device__ int   g_ccol[NW * CSR_CAP];
__device__ float g_cval[NW * CSR_CAP];

__device__ __forceinline__ float warp_sum(float v) {
#pragma unroll
    for (int o = 16; o; o >>= 1) v += __shfl_xor_sync(0xffffffffu, v, o);
    return v;
}

__device__ __forceinline__ float load_scalar(const void* p) {
    int v = *(const int*)p;
    if (v >= 0 && v <= 1000000) return (float)v;
    return *(const float*)p;
}

// SpMM one row via CSR with shfl-broadcast (proven r10/r14/r15). Regs out.
__device__ __forceinline__ void spmm_row_regs(const float* __restrict__ X,
                                              int row, int lane,
                                              float& a0, float& a1,
                                              float& a2, float& a3) {
    int nnz = g_ccnt[row];
    const int* cols = g_ccol + row * CSR_CAP;
    const float* vals = g_cval + row * CSR_CAP;
    int   c0 = (lane < nnz) ? cols[lane] : 0;
    float v0 = (lane < nnz) ? vals[lane] : 0.f;
    int   c1 = (lane + 32 < nnz) ? cols[lane + 32] : 0;
    float v1 = (lane + 32 < nnz) ? vals[lane + 32] : 0.f;
    int   c2 = (lane + 64 < nnz) ? cols[lane + 64] : 0;
    float v2 = (lane + 64 < nnz) ? vals[lane + 64] : 0.f;

    a0 = 0.f; a1 = 0.f; a2 = 0.f; a3 = 0.f;
    int lim0 = min(32, nnz);
    for (int s = 0; s < lim0; ++s) {
        int cc = __shfl_sync(0xffffffffu, c0, s);
        float vv = __shfl_sync(0xffffffffu, v0, s);
        const float* Xr = X + (size_t)cc * NF;
        a0 = fmaf(vv, Xr[lane], a0);
        a1 = fmaf(vv, Xr[lane + 32], a1);
        a2 = fmaf(vv, Xr[lane + 64], a2);
        if (lane < 4) a3 = fmaf(vv, Xr[lane + 96], a3);
    }
    if (nnz > 32) {
        int lim1 = min(32, nnz - 32);
        for (int s = 0; s < lim1; ++s) {
            int cc = __shfl_sync(0xffffffffu, c1, s);
            float vv = __shfl_sync(0xffffffffu, v1, s);
            const float* Xr = X + (size_t)cc * NF;
            a0 = fmaf(vv, Xr[lane], a0);
            a1 = fmaf(vv, Xr[lane + 32], a1);
            a2 = fmaf(vv, Xr[lane + 64], a2);
            if (lane < 4) a3 = fmaf(vv, Xr[lane + 96], a3);
        }
    }
    if (nnz > 64) {
        int lim2 = min(32, nnz - 64);
        for (int s = 0; s < lim2; ++s) {
            int cc = __shfl_sync(0xffffffffu, c2, s);
            float vv = __shfl_sync(0xffffffffu, v2, s);
            const float* Xr = X + (size_t)cc * NF;
            a0 = fmaf(vv, Xr[lane], a0);
            a1 = fmaf(vv, Xr[lane + 32], a1);
            a2 = fmaf(vv, Xr[lane + 64], a2);
            if (lane < 4) a3 = fmaf(vv, Xr[lane + 96], a3);
        }
    }
}

// Warp GEMV: row (in regs a0..a3, element k held by lane k%32 in chunk k/32)
// times sW[100x100] (+ sb bias or nullptr) -> out regs o0..o3 (col = lane+32j).
__device__ __forceinline__ void warp_gemv(const float* __restrict__ sW,
                                          const float* __restrict__ sb,
                                          int lane,
                                          float a0, float a1, float a2, float a3,
                                          float& o0, float& o1, float& o2, float& o3) {
    o0 = sb ? sb[lane] : 0.f;
    o1 = sb ? sb[lane + 32] : 0.f;
    o2 = sb ? sb[lane + 64] : 0.f;
    o3 = (sb && lane < 4) ? sb[lane + 96] : 0.f;
#pragma unroll 4
    for (int s = 0; s < 32; ++s) {
        float ak = __shfl_sync(0xffffffffu, a0, s);
        const float* Wk = sW + s * NF;
        o0 = fmaf(ak, Wk[lane], o0);
        o1 = fmaf(ak, Wk[lane + 32], o1);
        o2 = fmaf(ak, Wk[lane + 64], o2);
        if (lane < 4) o3 = fmaf(ak, Wk[lane + 96], o3);
    }
#pragma unroll 4
    for (int s = 0; s < 32; ++s) {
        float ak = __shfl_sync(0xffffffffu, a1, s);
        const float* Wk = sW + (32 + s) * NF;
        o0 = fmaf(ak, Wk[lane], o0);
        o1 = fmaf(ak, Wk[lane + 32], o1);
        o2 = fmaf(ak, Wk[lane + 64], o2);
        if (lane < 4) o3 = fmaf(ak, Wk[lane + 96], o3);
    }
#pragma unroll 4
    for (int s = 0; s < 32; ++s) {
        float ak = __shfl_sync(0xffffffffu, a2, s);
        const float* Wk = sW + (64 + s) * NF;
        o0 = fmaf(ak, Wk[lane], o0);
        o1 = fmaf(ak, Wk[lane + 32], o1);
        o2 = fmaf(ak, Wk[lane + 64], o2);
        if (lane < 4) o3 = fmaf(ak, Wk[lane + 96], o3);
    }
#pragma unroll
    for (int s = 0; s < 4; ++s) {
        float ak = __shfl_sync(0xffffffffu, a3, s);
        const float* Wk = sW + (96 + s) * NF;
        o0 = fmaf(ak, Wk[lane], o0);
        o1 = fmaf(ak, Wk[lane + 32], o1);
        o2 = fmaf(ak, Wk[lane + 64], o2);
        if (lane < 4) o3 = fmaf(ak, Wk[lane + 96], o3);
    }
}

// ---------------------------------------------------------------------------
// Streams + events (static init; not during capture)
// ---------------------------------------------------------------------------
struct SideRes {
    cudaStream_t s_side, s_a, s_b;
    cudaEvent_t fork, ev_z, ev3, ev_beta, ev_final;
    SideRes() {
        int lo = 0, hi = 0;
        cudaDeviceGetStreamPriorityRange(&lo, &hi);
        cudaStreamCreateWithPriority(&s_side, cudaStreamNonBlocking, lo);
        cudaStreamCreateWithFlags(&s_a, cudaStreamNonBlocking);
        cudaStreamCreateWithFlags(&s_b, cudaStreamNonBlocking);
        cudaEventCreateWithFlags(&fork, cudaEventDisableTiming);
        cudaEventCreateWithFlags(&ev_z, cudaEventDisableTiming);
        cudaEventCreateWithFlags(&ev3, cudaEventDisableTiming);
        cudaEventCreateWithFlags(&ev_beta, cudaEventDisableTiming);
        cudaEventCreateWithFlags(&ev_final, cudaEventDisableTiming);
    }
};
static SideRes g_sr;

// ---------------------------------------------------------------------------
// zev_zero — proven shape. Starts after prefix (ev3), r15 schedule.
// ---------------------------------------------------------------------------
#define ZA4 (100u * 160u * 210u)
#define ZB4 (100u * 840u * 250u)
#define ZT4 (ZA4 + ZB4)

__global__ void __launch_bounds__(256)
zev_zero(float* __restrict__ zev) {
    float4 z = {0.f, 0.f, 0.f, 0.f};
    float4* p = (float4*)zev;
    unsigned g = blockIdx.x * blockDim.x + threadIdx.x;
    unsigned stride = gridDim.x * blockDim.x;
    for (; g < ZT4; g += stride) {
        unsigned off4;
        if (g < ZA4) {
            unsigned d = g / 33600u;
            unsigned rem = g - d * 33600u;
            unsigned i = rem / 210u;
            unsigned q = rem - i * 210u;
            off4 = d * 250000u + i * 250u + 40u + q;
        } else {
            unsigned h = g - ZA4;
            unsigned d = h / 210000u;
            unsigned rem = h - d * 210000u;
            unsigned i2 = rem / 250u;
            unsigned q = rem - i2 * 250u;
            off4 = d * 250000u + (160u + i2) * 250u + q;
        }
        p[off4] = z;
    }
}

// ---------------------------------------------------------------------------
// prep_k (verbatim, proven)
// ---------------------------------------------------------------------------
__global__ void prep_k(const float* __restrict__ adj,
                       const float* __restrict__ wm, const float* __restrict__ Wbeta,
                       const void* ep, const void* eps) {
    int t = threadIdx.x, lane = t & 31, wid = t >> 5;
    if (blockIdx.x < 250) {
        int row = blockIdx.x * 4 + wid;
        const float* r = adj + (size_t)row * NW;
        int cnt = 0;
        for (int base = 0; base < NW; base += 32) {
            int c = base + lane;
            float v = (c < NW) ? r[c] : 0.f;
            unsigned m = __ballot_sync(0xffffffffu, v != 0.f);
            while (m) {
                int b = __ffs(m) - 1;
                m &= m - 1;
                float vb = __shfl_sync(0xffffffffu, v, b);
                if (lane == 0 && cnt < CSR_CAP) {
                    g_ccol[row * CSR_CAP + cnt] = base + b;
                    g_cval[row * CSR_CAP + cnt] = vb;
                }
                ++cnt;
            }
        }
        if (lane == 0) g_ccnt[row] = min(cnt, CSR_CAP);
    } else if (t < NF) {
        float e1 = load_scalar(ep), e2 = load_scalar(eps);
        int j = (int)rintf((e1 / e2) * 0.3f * (float)NF);
        float wi = wm[t];
        int rank = 0;
        for (int l = 0; l < NF; ++l) {
            float wl = wm[l];
            if (wl < wi || (wl == wi && l < t)) ++rank;
        }
        g_wp[t] = (rank >= j) ? Wbeta[t] : 0.f;
    }
}

// ---------------------------------------------------------------------------
// fuseA: warp-per-row. H1 = relu( (adj @ bows) @ Wg1 ). 125 blocks x 256.
// ---------------------------------------------------------------------------
__global__ void __launch_bounds__(256)
fuseA(const float* __restrict__ bows, const float* __restrict__ Wg1,
      float* __restrict__ H1) {
    __shared__ __align__(16) float sW[NF * NF];
    int t = threadIdx.x, lane = t & 31, w = t >> 5;
    int row = blockIdx.x * 8 + w;

    for (int i = t; i < NF * NF / 4; i += 256)
        ((float4*)sW)[i] = ((const float4*)Wg1)[i];

    float a0, a1, a2, a3;
    spmm_row_regs(bows, row, lane, a0, a1, a2, a3);   // R row = (adj@bows)[row]
    __syncthreads();

    float o0, o1, o2, o3;
    warp_gemv(sW, nullptr, lane, a0, a1, a2, a3, o0, o1, o2, o3);

    float* Hr = H1 + (size_t)row * NF;
    Hr[lane] = fmaxf(o0, 0.f);
    Hr[lane + 32] = fmaxf(o1, 0.f);
    Hr[lane + 64] = fmaxf(o2, 0.f);
    if (lane < 4) Hr[lane + 96] = fmaxf(o3, 0.f);
}

// ---------------------------------------------------------------------------
// fuseB: warp-per-row. S=(adj@H1); H=S@Wg2 -> oH; y=H.wp;
// E1=relu(H@Wh1+b1); heli=l2norm(relu(E1@Wh2+b2)). 125 blocks x 256.
// ---------------------------------------------------------------------------
__global__ void __launch_bounds__(256)
fuseB(const float* __restrict__ H1,
      const float* __restrict__ Wg2,
      const float* __restrict__ Wh1, const float* __restrict__ bh1,
      const float* __restrict__ Wh2, const float* __restrict__ bh2,
      float* __restrict__ oH, float* __restrict__ heli) {
    __shared__ __align__(16) float sW[NF * NF];
    __shared__ float sb[NF];
    int t = threadIdx.x, lane = t & 31, w = t >> 5;
    int row = blockIdx.x * 8 + w;

    // stage Wg2
    for (int i = t; i < NF * NF / 4; i += 256)
        ((float4*)sW)[i] = ((const float4*)Wg2)[i];

    float s0, s1, s2, s3;
    spmm_row_regs(H1, row, lane, s0, s1, s2, s3);     // S row = (adj@H1)[row]
    __syncthreads();

    // H = S @ Wg2
    float h0, h1, h2, h3;
    warp_gemv(sW, nullptr, lane, s0, s1, s2, s3, h0, h1, h2, h3);
    {
        float* Hr = oH + (size_t)row * NF;
        Hr[lane] = h0; Hr[lane + 32] = h1; Hr[lane + 64] = h2;
        if (lane < 4) Hr[lane + 96] = h3;
        float p = h0 * g_wp[lane] + h1 * g_wp[lane + 32] + h2 * g_wp[lane + 64];
        if (lane < 4) p = fmaf(h3, g_wp[lane + 96], p);
        p = warp_sum(p);
        if (lane == 0) g_y[row] = p;
    }
    __syncthreads();

    // stage Wh1 + b1
    for (int i = t; i < NF * NF / 4; i += 256)
        ((float4*)sW)[i] = ((const float4*)Wh1)[i];
    if (t < NF) sb[t] = bh1[t];
    __syncthreads();

    float e0, e1, e2, e3;
    warp_gemv(sW, sb, lane, h0, h1, h2, h3, e0, e1, e2, e3);
    e0 = fmaxf(e0, 0.f); e1 = fmaxf(e1, 0.f);
    e2 = fmaxf(e2, 0.f); e3 = fmaxf(e3, 0.f);
    __syncthreads();

    // stage Wh2 + b2
    for (int i = t; i < NF * NF / 4; i += 256)
        ((float4*)sW)[i] = ((const float4*)Wh2)[i];
    if (t < NF) sb[t] = bh2[t];
    __syncthreads();

    float q0, q1, q2, q3;
    warp_gemv(sW, sb, lane, e0, e1, e2, e3, q0, q1, q2, q3);
    q0 = fmaxf(q0, 0.f); q1 = fmaxf(q1, 0.f);
    q2 = fmaxf(q2, 0.f); q3 = fmaxf(q3, 0.f);
    float ss = q0 * q0 + q1 * q1 + q2 * q2 + q3 * q3;
    ss = warp_sum(ss);
    float inv = 1.f / fmaxf(sqrtf(ss), 1e-12f);
    float* Cr = heli + (size_t)row * NF;
    Cr[lane] = q0 * inv; Cr[lane + 32] = q1 * inv; Cr[lane + 64] = q2 * inv;
    if (lane < 4) Cr[lane + 96] = q3 * inv;
}

// ---------------------------------------------------------------------------
// beta_norm (verbatim, proven)
// ---------------------------------------------------------------------------
__global__ void __launch_bounds__(1024)
beta_norm(float* __restrict__ oBeta) {
    __shared__ float red[1024];
    int t = threadIdx.x;
    float y = (t < NW) ? g_y[t] : 0.f;
    red[t] = y * y;
    __syncthreads();
    for (int s = 512; s; s >>= 1) {
        if (t < s) red[t] += red[t + s];
        __syncthreads();
    }
    float inv = 1.f / fmaxf(sqrtf(red[0]), 1e-12f);
    if (t < NW) oBeta[t] = y * inv;
}

// ---------------------------------------------------------------------------
// gemm_nt_relu (round-2 VERBATIM — protected)
// ---------------------------------------------------------------------------
__global__ void gemm_nt_relu(const float* __restrict__ A, float* __restrict__ C,
                             int M, int K) {
    __shared__ float sA[64][21];
    __shared__ float sB[64][21];
    int tx = threadIdx.x, ty = threadIdx.y;
    int tid = ty * 16 + tx;
    int ib = blockIdx.y * 64, jb = blockIdx.x * 64;
    float acc[4][4] = {};
    for (int k0 = 0; k0 < K; k0 += 20) {
        for (int l = tid; l < 64 * 20; l += 256) {
            int r = l / 20, c = l - r * 20;
            int kk = k0 + c;
            sA[r][c] = (ib + r < M && kk < K) ? A[(size_t)(ib + r) * K + kk] : 0.f;
            sB[r][c] = (jb + r < M && kk < K) ? A[(size_t)(jb + r) * K + kk] : 0.f;
        }
        __syncthreads();
#pragma unroll
        for (int kk = 0; kk < 20; ++kk) {
            float a[4], b[4];
#pragma unroll
            for (int r = 0; r < 4; ++r) a[r] = sA[ty * 4 + r][kk];
#pragma unroll
            for (int c = 0; c < 4; ++c) b[c] = sB[tx * 4 + c][kk];
#pragma unroll
            for (int r = 0; r < 4; ++r)
#pragma unroll
                for (int c = 0; c < 4; ++c) acc[r][c] = fmaf(a[r], b[c], acc[r][c]);
        }
        __syncthreads();
    }
#pragma unroll
    for (int r = 0; r < 4; ++r) {
        int i = ib + ty * 4 + r;
        if (i >= M) continue;
#pragma unroll
        for (int c = 0; c < 4; ++c) {
            int j = jb + tx * 4 + c;
            if (j >= M) continue;
            C[(size_t)i * M + j] = fmaxf(acc[r][c], 0.f);
        }
    }
}

// ---------------------------------------------------------------------------
// doc_k (verbatim, proven)
// ---------------------------------------------------------------------------
__global__ void __launch_bounds__(512)
doc_k(const float* __restrict__ masks, const float* __restrict__ H,
      const float* __restrict__ heli, const float* __restrict__ beta_,
      const float* __restrict__ W_mu2, const float* __restrict__ b_mu2,
      const float* __restrict__ W_eta2, const float* __restrict__ b_eta2,
      const float* __restrict__ W_gm2, const float* __restrict__ b_gm2,
      const float* __restrict__ img, const float* __restrict__ W_m1,
      const float* __restrict__ b_m1, const float* __restrict__ W_m2,
      const float* __restrict__ b_m2,
      float* __restrict__ oLam, float* __restrict__ oEta,
      float* __restrict__ oGamma) {
    __shared__ int   cols[KMAX];
    __shared__ float red[512];
    __shared__ float hp[128];
    __shared__ float simg[TIw];
    __shared__ float sres[8];
    __shared__ int s_cnt;

    int d = blockIdx.x, t = threadIdx.x, lane = t & 31, wid = t >> 5;

    if (wid == 0) {
        const float* mrow = masks + (size_t)d * NW;
        int cnt = 0;
        for (int base = 0; base < NW; base += 32) {
            int c = base + lane;
            float v = (c < NW) ? mrow[c] : 0.f;
            unsigned m = __ballot_sync(0xffffffffu, v != 0.f);
            while (m) {
                int b = __ffs(m) - 1;
                m &= m - 1;
                if (lane == 0 && cnt < KMAX) cols[cnt] = base + b;
                ++cnt;
            }
        }
        if (lane == 0) s_cnt = min(cnt, KMAX);
    }
    __syncthreads();
    int cnt = s_cnt;
    float fk = (float)cnt;

    float sv = 0.f;
    if (t < NF) {
        float hpv = 0.f;
#pragma unroll 4
        for (int q = 0; q < cnt; ++q) {
            int c = cols[q];
            hpv += H[(size_t)c * NF + t];
            sv += heli[(size_t)c * NF + t];
        }
        hp[t] = hpv / fmaxf(fk, 1.f);
    }
    red[t] = (t < NF) ? sv * sv : 0.f;
    __syncthreads();
    for (int s = 256; s; s >>= 1) { if (t < s) red[t] += red[t + s]; __syncthreads(); }
    if (t == 0) sres[0] = red[0];
    __syncthreads();

    red[t] = (t < cnt) ? beta_[cols[t]] : 0.f;
    __syncthreads();
    for (int s = 256; s; s >>= 1) { if (t < s) red[t] += red[t + s]; __syncthreads(); }
    if (t == 0) sres[1] = red[0];
    __syncthreads();

    float hpt = (t < NF) ? hp[t] : 0.f;
    red[t] = (t < NF) ? hpt * W_mu2[t] : 0.f;
    __syncthreads();
    for (int s = 256; s; s >>= 1) { if (t < s) red[t] += red[t + s]; __syncthreads(); }
    if (t == 0) sres[2] = fmaxf(red[0] + b_mu2[0], 0.f);
    __syncthreads();
    red[t] = (t < NF) ? hpt * W_eta2[t] : 0.f;
    __syncthreads();
    for (int s = 256; s; s >>= 1) { if (t < s) red[t] += red[t + s]; __syncthreads(); }
    if (t == 0) sres[3] = fmaxf(red[0] + b_eta2[0], 0.f);
    __syncthreads();
    red[t] = (t < NF) ? hpt * W_gm2[t] : 0.f;
    __syncthreads();
    for (int s = 256; s; s >>= 1) { if (t < s) red[t] += red[t + s]; __syncthreads(); }
    if (t == 0) sres[4] = fmaxf(red[0] + b_gm2[0], 0.f);
    __syncthreads();

    for (int k = t; k < TIw; k += 512) simg[k] = img[(size_t)d * TIw + k];
    __syncthreads();
    float contrib = 0.f;
    if (t < HDw) {
        float h0 = b_m1[t], h1 = 0.f, h2 = 0.f, h3 = 0.f;
#pragma unroll 4
        for (int k = 0; k < TIw; k += 4) {
            h0 = fmaf(simg[k],     W_m1[(size_t)k * HDw + t],       h0);
            h1 = fmaf(simg[k + 1], W_m1[(size_t)(k + 1) * HDw + t], h1);
            h2 = fmaf(simg[k + 2], W_m1[(size_t)(k + 2) * HDw + t], h2);
            h3 = fmaf(simg[k + 3], W_m1[(size_t)(k + 3) * HDw + t], h3);
        }
        contrib = fmaxf((h0 + h1) + (h2 + h3), 0.f) * W_m2[t];
    }
    red[t] = contrib;
    __syncthreads();
    for (int s = 256; s; s >>= 1) { if (t < s) red[t] += red[t + s]; __syncthreads(); }

    if (t == 0) {
        float li = red[0] + b_m2[0];
        float Z = fmaxf(0.5f * (sres[0] - fk), 0.f);
        float inner = sres[2] + sres[1] + sres[3] * expf(-sres[4] * Z);
        float lt = 1.f / (1.f + expf(-inner));
        oLam[d] = 1.f / (1.f + expf(-(lt + li)));
        oEta[d] = sres[3];
        oGamma[d] = sres[4];
        g_kci[d] = cnt;
    }
}

// ---------------------------------------------------------------------------
// zev_patch (verbatim, proven). Disjoint from zev_zero's region.
// ---------------------------------------------------------------------------
__global__ void __launch_bounds__(256)
zev_patch(const float* __restrict__ oZ, float* __restrict__ zev) {
    unsigned g = blockIdx.x * 256u + threadIdx.x;
    if (g >= 640000u) return;
    unsigned d = g / 6400u;
    unsigned rem = g - d * 6400u;
    unsigned i = rem / 40u;
    unsigned q = rem - i * 40u;
    unsigned j0 = q << 2;
    int kd = g_kci[d];
    float4 v = {0.f, 0.f, 0.f, 0.f};
    if ((int)i < kd) {
        const float* zr = oZ + (size_t)i * NW + j0;
        float* vv = (float*)&v;
#pragma unroll
        for (int c = 0; c < 4; ++c) {
            int j = (int)j0 + c;
            if (j < kd && j != (int)i) {
                float tt = 2.f - 2.f * zr[c];
                vv[c] = expf(-tt * tt);
            }
        }
    }
    *(float4*)(zev + (size_t)d * NW * NW + (size_t)i * NW + j0) = v;
}

// ---------------------------------------------------------------------------
// Host launch — depth-3 prefix, r15 tail schedule.
// ---------------------------------------------------------------------------
extern "C" void kernel_launch(void* const* d_in, const int* in_sizes, int n_in,
                              void* d_out, int out_size) {
    (void)in_sizes; (void)n_in; (void)out_size;
    const void*  epoch  = d_in[0];
    const void*  epochs = d_in[1];
    const float* adj    = (const float*)d_in[2];
    const float* masks  = (const float*)d_in[3];
    const float* bows   = (const float*)d_in[4];
    const float* img    = (const float*)d_in[5];
    const float* W_g1   = (const float*)d_in[6];
    const float* W_g2   = (const float*)d_in[7];
    const float* W_h1   = (const float*)d_in[8];
    const float* b_h1   = (const float*)d_in[9];
    const float* W_h2   = (const float*)d_in[10];
    const float* b_h2   = (const float*)d_in[11];
    const float* W_mu2  = (const float*)d_in[12];
    const float* b_mu2  = (const float*)d_in[13];
    const float* W_eta2 = (const float*)d_in[14];
    const float* b_eta2 = (const float*)d_in[15];
    const float* W_gm2  = (const float*)d_in[16];
    const float* b_gm2  = (const float*)d_in[17];
    const float* w_m    = (const float*)d_in[18];
    const float* W_beta = (const float*)d_in[19];
    const float* W_m1   = (const float*)d_in[20];
    const float* b_m1   = (const float*)d_in[21];
    const float* W_m2   = (const float*)d_in[22];
    const float* b_m2   = (const float*)d_in[23];

    float* out = (float*)d_out;
    float* oLam   = out + OFF_LAM;
    float* oZ     = out + OFF_ZMAT;
    float* oBeta  = out + OFF_BETA;
    float* oGamma = out + OFF_GAMMA;
    float* oEta   = out + OFF_ETA;
    float* oZev   = out + OFF_ZEV;
    float* oH     = out + OFF_H;

    float *pH1, *pHeli;
    cudaGetSymbolAddress((void**)&pH1, g_H1);
    cudaGetSymbolAddress((void**)&pHeli, g_heli);

    // fork from capture stream
    cudaEventRecord(g_sr.fork, 0);

    // ---- phase 1: uncontended prefix (depth 3) ----
    cudaStreamWaitEvent(g_sr.s_a, g_sr.fork, 0);
    prep_k<<<251, 128, 0, g_sr.s_a>>>(adj, w_m, W_beta, epoch, epochs);
    fuseA<<<125, 256, 0, g_sr.s_a>>>(bows, W_g1, pH1);
    fuseB<<<125, 256, 0, g_sr.s_a>>>(pH1, W_g2, W_h1, b_h1, W_h2, b_h2, oH, pHeli);
    cudaEventRecord(g_sr.ev3, g_sr.s_a);

    // ---- phase 2: fill overlaps the tail ----
    cudaStreamWaitEvent(g_sr.s_side, g_sr.ev3, 0);
    zev_zero<<<296, 256, 0, g_sr.s_side>>>(oZev);
    cudaEventRecord(g_sr.ev_z, g_sr.s_side);

    cudaStreamWaitEvent(g_sr.s_b, g_sr.ev3, 0);
    beta_norm<<<1, 1024, 0, g_sr.s_b>>>(oBeta);
    doc_k<<<ND, 512, 0, g_sr.s_b>>>(masks, oH, pHeli, oBeta,
                                    W_mu2, b_mu2, W_eta2, b_eta2, W_gm2, b_gm2,
                                    img, W_m1, b_m1, W_m2, b_m2,
                                    oLam, oEta, oGamma);
    cudaEventRecord(g_sr.ev_beta, g_sr.s_b);

    {
        dim3 grid((NW + 63) / 64, (NW + 63) / 64);
        dim3 block(16, 16);
        gemm_nt_relu<<<grid, block, 0, g_sr.s_a>>>(pHeli, oZ, NW, NF);
    }

    // patch: needs Z_ (in-order on s_a) + kci; disjoint from fill region.
    cudaStreamWaitEvent(g_sr.s_a, g_sr.ev_beta, 0);
    zev_patch<<<2500, 256, 0, g_sr.s_a>>>(oZ, oZev);
    cudaEventRecord(g_sr.ev_final, g_sr.s_a);

    // join
    cudaStreamWaitEvent(0, g_sr.ev_final, 0);
    cudaStreamWaitEvent(0, g_sr.ev_z, 0);
}

// round 17
// speedup vs baseline: 1.3234x; 1.1903x over previous
#include <cuda_runtime.h>
#include <cuda_bf16.h>
#include <math.h>
#include <stdint.h>

// ---------------------------------------------------------------------------
// Problem constants
// ---------------------------------------------------------------------------
#define NW 1000
#define ND 100
#define NF 100
#define TIw 512
#define HDw 128

// Output layout (concatenated f32)
#define OFF_LAM   0
#define OFF_ZMAT  100
#define OFF_BETA  1000100
#define OFF_GAMMA 1001100
#define OFF_ETA   1001200
#define OFF_ZEV   1001300
#define OFF_H     101001300

#define KMAX 160

// ---------------------------------------------------------------------------
// Device scratch
// ---------------------------------------------------------------------------
__device__ __align__(16) float g_H1[NW * NF];
__device__ __align__(16) float g_heli[NW * NF];
__device__ float g_y[NW];
__device__ float g_wp[NF];
__device__ float g_ynorm2;
__device__ int   g_kci[ND];

#define CSR_CAP 96
__device__ int   g_ccnt[NW];
__device__ int   g_ccol[NW * CSR_CAP];
__device__ float g_cval[NW * CSR_CAP];

__device__ __forceinline__ float warp_sum(float v) {
#pragma unroll
    for (int o = 16; o; o >>= 1) v += __shfl_xor_sync(0xffffffffu, v, o);
    return v;
}

__device__ __forceinline__ float load_scalar(const void* p) {
    int v = *(const int*)p;
    if (v >= 0 && v <= 1000000) return (float)v;
    return *(const float*)p;
}

// SpMM one row via CSR with shfl-broadcast (proven). Results in regs.
__device__ __forceinline__ void spmm_row_regs(const float* __restrict__ X,
                                              int row, int lane,
                                              float& a0, float& a1,
                                              float& a2, float& a3) {
    int nnz = g_ccnt[row];
    const int* cols = g_ccol + row * CSR_CAP;
    const float* vals = g_cval + row * CSR_CAP;
    int   c0 = (lane < nnz) ? cols[lane] : 0;
    float v0 = (lane < nnz) ? vals[lane] : 0.f;
    int   c1 = (lane + 32 < nnz) ? cols[lane + 32] : 0;
    float v1 = (lane + 32 < nnz) ? vals[lane + 32] : 0.f;
    int   c2 = (lane + 64 < nnz) ? cols[lane + 64] : 0;
    float v2 = (lane + 64 < nnz) ? vals[lane + 64] : 0.f;

    a0 = 0.f; a1 = 0.f; a2 = 0.f; a3 = 0.f;
    int lim0 = min(32, nnz);
    for (int s = 0; s < lim0; ++s) {
        int cc = __shfl_sync(0xffffffffu, c0, s);
        float vv = __shfl_sync(0xffffffffu, v0, s);
        const float* Xr = X + (size_t)cc * NF;
        a0 = fmaf(vv, Xr[lane], a0);
        a1 = fmaf(vv, Xr[lane + 32], a1);
        a2 = fmaf(vv, Xr[lane + 64], a2);
        if (lane < 4) a3 = fmaf(vv, Xr[lane + 96], a3);
    }
    if (nnz > 32) {
        int lim1 = min(32, nnz - 32);
        for (int s = 0; s < lim1; ++s) {
            int cc = __shfl_sync(0xffffffffu, c1, s);
            float vv = __shfl_sync(0xffffffffu, v1, s);
            const float* Xr = X + (size_t)cc * NF;
            a0 = fmaf(vv, Xr[lane], a0);
            a1 = fmaf(vv, Xr[lane + 32], a1);
            a2 = fmaf(vv, Xr[lane + 64], a2);
            if (lane < 4) a3 = fmaf(vv, Xr[lane + 96], a3);
        }
    }
    if (nnz > 64) {
        int lim2 = min(32, nnz - 64);
        for (int s = 0; s < lim2; ++s) {
            int cc = __shfl_sync(0xffffffffu, c2, s);
            float vv = __shfl_sync(0xffffffffu, v2, s);
            const float* Xr = X + (size_t)cc * NF;
            a0 = fmaf(vv, Xr[lane], a0);
            a1 = fmaf(vv, Xr[lane + 32], a1);
            a2 = fmaf(vv, Xr[lane + 64], a2);
            if (lane < 4) a3 = fmaf(vv, Xr[lane + 96], a3);
        }
    }
}

// Warp GEMV (proven r16): row regs x sW[100x100] (+bias) -> out regs.
__device__ __forceinline__ void warp_gemv(const float* __restrict__ sW,
                                          const float* __restrict__ sb,
                                          int lane,
                                          float a0, float a1, float a2, float a3,
                                          float& o0, float& o1, float& o2, float& o3) {
    o0 = sb ? sb[lane] : 0.f;
    o1 = sb ? sb[lane + 32] : 0.f;
    o2 = sb ? sb[lane + 64] : 0.f;
    o3 = (sb && lane < 4) ? sb[lane + 96] : 0.f;
#pragma unroll 4
    for (int s = 0; s < 32; ++s) {
        float ak = __shfl_sync(0xffffffffu, a0, s);
        const float* Wk = sW + s * NF;
        o0 = fmaf(ak, Wk[lane], o0);
        o1 = fmaf(ak, Wk[lane + 32], o1);
        o2 = fmaf(ak, Wk[lane + 64], o2);
        if (lane < 4) o3 = fmaf(ak, Wk[lane + 96], o3);
    }
#pragma unroll 4
    for (int s = 0; s < 32; ++s) {
        float ak = __shfl_sync(0xffffffffu, a1, s);
        const float* Wk = sW + (32 + s) * NF;
        o0 = fmaf(ak, Wk[lane], o0);
        o1 = fmaf(ak, Wk[lane + 32], o1);
        o2 = fmaf(ak, Wk[lane + 64], o2);
        if (lane < 4) o3 = fmaf(ak, Wk[lane + 96], o3);
    }
#pragma unroll 4
    for (int s = 0; s < 32; ++s) {
        float ak = __shfl_sync(0xffffffffu, a2, s);
        const float* Wk = sW + (64 + s) * NF;
        o0 = fmaf(ak, Wk[lane], o0);
        o1 = fmaf(ak, Wk[lane + 32], o1);
        o2 = fmaf(ak, Wk[lane + 64], o2);
        if (lane < 4) o3 = fmaf(ak, Wk[lane + 96], o3);
    }
#pragma unroll
    for (int s = 0; s < 4; ++s) {
        float ak = __shfl_sync(0xffffffffu, a3, s);
        const float* Wk = sW + (96 + s) * NF;
        o0 = fmaf(ak, Wk[lane], o0);
        o1 = fmaf(ak, Wk[lane + 32], o1);
        o2 = fmaf(ak, Wk[lane + 64], o2);
        if (lane < 4) o3 = fmaf(ak, Wk[lane + 96], o3);
    }
}

// ---------------------------------------------------------------------------
// Streams + events (static init; not during capture)
// ---------------------------------------------------------------------------
struct SideRes {
    cudaStream_t s_side, s_a, s_b;
    cudaEvent_t fork, ev_z, ev3, ev_doc, ev_final;
    SideRes() {
        int lo = 0, hi = 0;
        cudaDeviceGetStreamPriorityRange(&lo, &hi);
        cudaStreamCreateWithPriority(&s_side, cudaStreamNonBlocking, lo);
        cudaStreamCreateWithFlags(&s_a, cudaStreamNonBlocking);
        cudaStreamCreateWithFlags(&s_b, cudaStreamNonBlocking);
        cudaEventCreateWithFlags(&fork, cudaEventDisableTiming);
        cudaEventCreateWithFlags(&ev_z, cudaEventDisableTiming);
        cudaEventCreateWithFlags(&ev3, cudaEventDisableTiming);
        cudaEventCreateWithFlags(&ev_doc, cudaEventDisableTiming);
        cudaEventCreateWithFlags(&ev_final, cudaEventDisableTiming);
    }
};
static SideRes g_sr;

// ---------------------------------------------------------------------------
// zev_zero — proven shape (296 blk). Starts at t=0 (overlaps the prefix).
// ---------------------------------------------------------------------------
#define ZA4 (100u * 160u * 210u)
#define ZB4 (100u * 840u * 250u)
#define ZT4 (ZA4 + ZB4)

__global__ void __launch_bounds__(256)
zev_zero(float* __restrict__ zev) {
    float4 z = {0.f, 0.f, 0.f, 0.f};
    float4* p = (float4*)zev;
    unsigned g = blockIdx.x * blockDim.x + threadIdx.x;
    unsigned stride = gridDim.x * blockDim.x;
    for (; g < ZT4; g += stride) {
        unsigned off4;
        if (g < ZA4) {
            unsigned d = g / 33600u;
            unsigned rem = g - d * 33600u;
            unsigned i = rem / 210u;
            unsigned q = rem - i * 210u;
            off4 = d * 250000u + i * 250u + 40u + q;
        } else {
            unsigned h = g - ZA4;
            unsigned d = h / 210000u;
            unsigned rem = h - d * 210000u;
            unsigned i2 = rem / 250u;
            unsigned q = rem - i2 * 250u;
            off4 = d * 250000u + (160u + i2) * 250u + q;
        }
        p[off4] = z;
    }
}

// ---------------------------------------------------------------------------
// prep_k: CSR gather + prune mask + zero ynorm2 (every launch: replay-safe)
// ---------------------------------------------------------------------------
__global__ void prep_k(const float* __restrict__ adj,
                       const float* __restrict__ wm, const float* __restrict__ Wbeta,
                       const void* ep, const void* eps) {
    int t = threadIdx.x, lane = t & 31, wid = t >> 5;
    if (blockIdx.x < 250) {
        int row = blockIdx.x * 4 + wid;
        const float* r = adj + (size_t)row * NW;
        int cnt = 0;
        for (int base = 0; base < NW; base += 32) {
            int c = base + lane;
            float v = (c < NW) ? r[c] : 0.f;
            unsigned m = __ballot_sync(0xffffffffu, v != 0.f);
            while (m) {
                int b = __ffs(m) - 1;
                m &= m - 1;
                float vb = __shfl_sync(0xffffffffu, v, b);
                if (lane == 0 && cnt < CSR_CAP) {
                    g_ccol[row * CSR_CAP + cnt] = base + b;
                    g_cval[row * CSR_CAP + cnt] = vb;
                }
                ++cnt;
            }
        }
        if (lane == 0) g_ccnt[row] = min(cnt, CSR_CAP);
    } else {
        if (t < NF) {
            float e1 = load_scalar(ep), e2 = load_scalar(eps);
            int j = (int)rintf((e1 / e2) * 0.3f * (float)NF);
            float wi = wm[t];
            int rank = 0;
            for (int l = 0; l < NF; ++l) {
                float wl = wm[l];
                if (wl < wi || (wl == wi && l < t)) ++rank;
            }
            g_wp[t] = (rank >= j) ? Wbeta[t] : 0.f;
        }
        if (t == 100) g_ynorm2 = 0.f;
    }
}

// ---------------------------------------------------------------------------
// fuseA (r16 verbatim): H1 = relu( (adj @ bows) @ Wg1 ). 125 x 256.
// ---------------------------------------------------------------------------
__global__ void __launch_bounds__(256)
fuseA(const float* __restrict__ bows, const float* __restrict__ Wg1,
      float* __restrict__ H1) {
    __shared__ __align__(16) float sW[NF * NF];
    int t = threadIdx.x, lane = t & 31, w = t >> 5;
    int row = blockIdx.x * 8 + w;

    for (int i = t; i < NF * NF / 4; i += 256)
        ((float4*)sW)[i] = ((const float4*)Wg1)[i];

    float a0, a1, a2, a3;
    spmm_row_regs(bows, row, lane, a0, a1, a2, a3);
    __syncthreads();

    float o0, o1, o2, o3;
    warp_gemv(sW, nullptr, lane, a0, a1, a2, a3, o0, o1, o2, o3);

    float* Hr = H1 + (size_t)row * NF;
    Hr[lane] = fmaxf(o0, 0.f);
    Hr[lane + 32] = fmaxf(o1, 0.f);
    Hr[lane + 64] = fmaxf(o2, 0.f);
    if (lane < 4) Hr[lane + 96] = fmaxf(o3, 0.f);
}

// ---------------------------------------------------------------------------
// fuseB (r16 + atomic ||y||^2): 125 x 256.
// ---------------------------------------------------------------------------
__global__ void __launch_bounds__(256)
fuseB(const float* __restrict__ H1,
      const float* __restrict__ Wg2,
      const float* __restrict__ Wh1, const float* __restrict__ bh1,
      const float* __restrict__ Wh2, const float* __restrict__ bh2,
      float* __restrict__ oH, float* __restrict__ heli) {
    __shared__ __align__(16) float sW[NF * NF];
    __shared__ float sb[NF];
    int t = threadIdx.x, lane = t & 31, w = t >> 5;
    int row = blockIdx.x * 8 + w;

    for (int i = t; i < NF * NF / 4; i += 256)
        ((float4*)sW)[i] = ((const float4*)Wg2)[i];

    float s0, s1, s2, s3;
    spmm_row_regs(H1, row, lane, s0, s1, s2, s3);
    __syncthreads();

    float h0, h1, h2, h3;
    warp_gemv(sW, nullptr, lane, s0, s1, s2, s3, h0, h1, h2, h3);
    {
        float* Hr = oH + (size_t)row * NF;
        Hr[lane] = h0; Hr[lane + 32] = h1; Hr[lane + 64] = h2;
        if (lane < 4) Hr[lane + 96] = h3;
        float p = h0 * g_wp[lane] + h1 * g_wp[lane + 32] + h2 * g_wp[lane + 64];
        if (lane < 4) p = fmaf(h3, g_wp[lane + 96], p);
        p = warp_sum(p);
        if (lane == 0) {
            g_y[row] = p;
            atomicAdd(&g_ynorm2, p * p);
        }
    }
    __syncthreads();

    for (int i = t; i < NF * NF / 4; i += 256)
        ((float4*)sW)[i] = ((const float4*)Wh1)[i];
    if (t < NF) sb[t] = bh1[t];
    __syncthreads();

    float e0, e1, e2, e3;
    warp_gemv(sW, sb, lane, h0, h1, h2, h3, e0, e1, e2, e3);
    e0 = fmaxf(e0, 0.f); e1 = fmaxf(e1, 0.f);
    e2 = fmaxf(e2, 0.f); e3 = fmaxf(e3, 0.f);
    __syncthreads();

    for (int i = t; i < NF * NF / 4; i += 256)
        ((float4*)sW)[i] = ((const float4*)Wh2)[i];
    if (t < NF) sb[t] = bh2[t];
    __syncthreads();

    float q0, q1, q2, q3;
    warp_gemv(sW, sb, lane, e0, e1, e2, e3, q0, q1, q2, q3);
    q0 = fmaxf(q0, 0.f); q1 = fmaxf(q1, 0.f);
    q2 = fmaxf(q2, 0.f); q3 = fmaxf(q3, 0.f);
    float ss = q0 * q0 + q1 * q1 + q2 * q2 + q3 * q3;
    ss = warp_sum(ss);
    float inv = 1.f / fmaxf(sqrtf(ss), 1e-12f);
    float* Cr = heli + (size_t)row * NF;
    Cr[lane] = q0 * inv; Cr[lane + 32] = q1 * inv; Cr[lane + 64] = q2 * inv;
    if (lane < 4) Cr[lane + 96] = q3 * inv;
}

// ---------------------------------------------------------------------------
// gemm_nt_relu (round-2 VERBATIM — protected)
// ---------------------------------------------------------------------------
__global__ void gemm_nt_relu(const float* __restrict__ A, float* __restrict__ C,
                             int M, int K) {
    __shared__ float sA[64][21];
    __shared__ float sB[64][21];
    int tx = threadIdx.x, ty = threadIdx.y;
    int tid = ty * 16 + tx;
    int ib = blockIdx.y * 64, jb = blockIdx.x * 64;
    float acc[4][4] = {};
    for (int k0 = 0; k0 < K; k0 += 20) {
        for (int l = tid; l < 64 * 20; l += 256) {
            int r = l / 20, c = l - r * 20;
            int kk = k0 + c;
            sA[r][c] = (ib + r < M && kk < K) ? A[(size_t)(ib + r) * K + kk] : 0.f;
            sB[r][c] = (jb + r < M && kk < K) ? A[(size_t)(jb + r) * K + kk] : 0.f;
        }
        __syncthreads();
#pragma unroll
        for (int kk = 0; kk < 20; ++kk) {
            float a[4], b[4];
#pragma unroll
            for (int r = 0; r < 4; ++r) a[r] = sA[ty * 4 + r][kk];
#pragma unroll
            for (int c = 0; c < 4; ++c) b[c] = sB[tx * 4 + c][kk];
#pragma unroll
            for (int r = 0; r < 4; ++r)
#pragma unroll
                for (int c = 0; c < 4; ++c) acc[r][c] = fmaf(a[r], b[c], acc[r][c]);
        }
        __syncthreads();
    }
#pragma unroll
    for (int r = 0; r < 4; ++r) {
        int i = ib + ty * 4 + r;
        if (i >= M) continue;
#pragma unroll
        for (int c = 0; c < 4; ++c) {
            int j = jb + tx * 4 + c;
            if (j >= M) continue;
            C[(size_t)i * M + j] = fmaxf(acc[r][c], 0.f);
        }
    }
}

// ---------------------------------------------------------------------------
// doc_k: per doc; beta on the fly from g_y * inv_norm; writes oBeta slice.
// Image MLP parallelized over all 512 threads (4 k-groups x 128 cols).
// ---------------------------------------------------------------------------
__global__ void __launch_bounds__(512)
doc_k(const float* __restrict__ masks, const float* __restrict__ H,
      const float* __restrict__ heli,
      const float* __restrict__ W_mu2, const float* __restrict__ b_mu2,
      const float* __restrict__ W_eta2, const float* __restrict__ b_eta2,
      const float* __restrict__ W_gm2, const float* __restrict__ b_gm2,
      const float* __restrict__ img, const float* __restrict__ W_m1,
      const float* __restrict__ b_m1, const float* __restrict__ W_m2,
      const float* __restrict__ b_m2,
      float* __restrict__ oLam, float* __restrict__ oEta,
      float* __restrict__ oGamma, float* __restrict__ oBeta) {
    __shared__ int   cols[KMAX];
    __shared__ float red[512];
    __shared__ float hp[128];
    __shared__ float simg[TIw];
    __shared__ float sres[8];
    __shared__ int s_cnt;

    int d = blockIdx.x, t = threadIdx.x, lane = t & 31, wid = t >> 5;

    float yinv = 1.f / fmaxf(sqrtf(g_ynorm2), 1e-12f);
    if (t < 10) {
        int i = d * 10 + t;
        oBeta[i] = g_y[i] * yinv;     // beta_ output, 10 entries per block
    }

    if (wid == 0) {
        const float* mrow = masks + (size_t)d * NW;
        int cnt = 0;
        for (int base = 0; base < NW; base += 32) {
            int c = base + lane;
            float v = (c < NW) ? mrow[c] : 0.f;
            unsigned m = __ballot_sync(0xffffffffu, v != 0.f);
            while (m) {
                int b = __ffs(m) - 1;
                m &= m - 1;
                if (lane == 0 && cnt < KMAX) cols[cnt] = base + b;
                ++cnt;
            }
        }
        if (lane == 0) s_cnt = min(cnt, KMAX);
    }
    __syncthreads();
    int cnt = s_cnt;
    float fk = (float)cnt;

    float sv = 0.f;
    if (t < NF) {
        float hpv = 0.f;
#pragma unroll 4
        for (int q = 0; q < cnt; ++q) {
            int c = cols[q];
            hpv += H[(size_t)c * NF + t];
            sv += heli[(size_t)c * NF + t];
        }
        hp[t] = hpv / fmaxf(fk, 1.f);
    }
    red[t] = (t < NF) ? sv * sv : 0.f;
    __syncthreads();
    for (int s = 256; s; s >>= 1) { if (t < s) red[t] += red[t + s]; __syncthreads(); }
    if (t == 0) sres[0] = red[0];
    __syncthreads();

    // beta_doc = sum over cols of y[c] * yinv
    red[t] = (t < cnt) ? g_y[cols[t]] : 0.f;
    __syncthreads();
    for (int s = 256; s; s >>= 1) { if (t < s) red[t] += red[t + s]; __syncthreads(); }
    if (t == 0) sres[1] = red[0] * yinv;
    __syncthreads();

    float hpt = (t < NF) ? hp[t] : 0.f;
    red[t] = (t < NF) ? hpt * W_mu2[t] : 0.f;
    __syncthreads();
    for (int s = 256; s; s >>= 1) { if (t < s) red[t] += red[t + s]; __syncthreads(); }
    if (t == 0) sres[2] = fmaxf(red[0] + b_mu2[0], 0.f);
    __syncthreads();
    red[t] = (t < NF) ? hpt * W_eta2[t] : 0.f;
    __syncthreads();
    for (int s = 256; s; s >>= 1) { if (t < s) red[t] += red[t + s]; __syncthreads(); }
    if (t == 0) sres[3] = fmaxf(red[0] + b_eta2[0], 0.f);
    __syncthreads();
    red[t] = (t < NF) ? hpt * W_gm2[t] : 0.f;
    __syncthreads();
    for (int s = 256; s; s >>= 1) { if (t < s) red[t] += red[t + s]; __syncthreads(); }
    if (t == 0) sres[4] = fmaxf(red[0] + b_gm2[0], 0.f);
    __syncthreads();

    // image MLP: all 512 threads; group g handles k in [g*128, g*128+128)
    for (int k = t; k < TIw; k += 512) simg[k] = img[(size_t)d * TIw + k];
    __syncthreads();
    {
        int grp = t >> 7;           // 0..3
        int col = t & 127;          // 0..127
        float part = 0.f;
        int k0 = grp * 128;
#pragma unroll 4
        for (int k = 0; k < 128; ++k)
            part = fmaf(simg[k0 + k], W_m1[(size_t)(k0 + k) * HDw + col], part);
        red[t] = part;
    }
    __syncthreads();
    float contrib = 0.f;
    if (t < HDw) {
        float hv = b_m1[t] + red[t] + red[t + 128] + red[t + 256] + red[t + 384];
        contrib = fmaxf(hv, 0.f) * W_m2[t];
    }
    __syncthreads();
    red[t] = (t < HDw) ? contrib : 0.f;
    __syncthreads();
    for (int s = 256; s; s >>= 1) { if (t < s) red[t] += red[t + s]; __syncthreads(); }

    if (t == 0) {
        float li = red[0] + b_m2[0];
        float Z = fmaxf(0.5f * (sres[0] - fk), 0.f);
        float inner = sres[2] + sres[1] + sres[3] * expf(-sres[4] * Z);
        float lt = 1.f / (1.f + expf(-inner));
        oLam[d] = 1.f / (1.f + expf(-(lt + li)));
        oEta[d] = sres[3];
        oGamma[d] = sres[4];
        g_kci[d] = cnt;
    }
}

// ---------------------------------------------------------------------------
// zev_patch (verbatim, proven). Disjoint from zev_zero's region.
// ---------------------------------------------------------------------------
__global__ void __launch_bounds__(256)
zev_patch(const float* __restrict__ oZ, float* __restrict__ zev) {
    unsigned g = blockIdx.x * 256u + threadIdx.x;
    if (g >= 640000u) return;
    unsigned d = g / 6400u;
    unsigned rem = g - d * 6400u;
    unsigned i = rem / 40u;
    unsigned q = rem - i * 40u;
    unsigned j0 = q << 2;
    int kd = g_kci[d];
    float4 v = {0.f, 0.f, 0.f, 0.f};
    if ((int)i < kd) {
        const float* zr = oZ + (size_t)i * NW + j0;
        float* vv = (float*)&v;
#pragma unroll
        for (int c = 0; c < 4; ++c) {
            int j = (int)j0 + c;
            if (j < kd && j != (int)i) {
                float tt = 2.f - 2.f * zr[c];
                vv[c] = expf(-tt * tt);
            }
        }
    }
    *(float4*)(zev + (size_t)d * NW * NW + (size_t)i * NW + j0) = v;
}

// ---------------------------------------------------------------------------
// Host launch — fill at t=0 overlapping everything; 7 nodes.
// ---------------------------------------------------------------------------
extern "C" void kernel_launch(void* const* d_in, const int* in_sizes, int n_in,
                              void* d_out, int out_size) {
    (void)in_sizes; (void)n_in; (void)out_size;
    const void*  epoch  = d_in[0];
    const void*  epochs = d_in[1];
    const float* adj    = (const float*)d_in[2];
    const float* masks  = (const float*)d_in[3];
    const float* bows   = (const float*)d_in[4];
    const float* img    = (const float*)d_in[5];
    const float* W_g1   = (const float*)d_in[6];
    const float* W_g2   = (const float*)d_in[7];
    const float* W_h1   = (const float*)d_in[8];
    const float* b_h1   = (const float*)d_in[9];
    const float* W_h2   = (const float*)d_in[10];
    const float* b_h2   = (const float*)d_in[11];
    const float* W_mu2  = (const float*)d_in[12];
    const float* b_mu2  = (const float*)d_in[13];
    const float* W_eta2 = (const float*)d_in[14];
    const float* b_eta2 = (const float*)d_in[15];
    const float* W_gm2  = (const float*)d_in[16];
    const float* b_gm2  = (const float*)d_in[17];
    const float* w_m    = (const float*)d_in[18];
    const float* W_beta = (const float*)d_in[19];
    const float* W_m1   = (const float*)d_in[20];
    const float* b_m1   = (const float*)d_in[21];
    const float* W_m2   = (const float*)d_in[22];
    const float* b_m2   = (const float*)d_in[23];

    float* out = (float*)d_out;
    float* oLam   = out + OFF_LAM;
    float* oZ     = out + OFF_ZMAT;
    float* oBeta  = out + OFF_BETA;
    float* oGamma = out + OFF_GAMMA;
    float* oEta   = out + OFF_ETA;
    float* oZev   = out + OFF_ZEV;
    float* oH     = out + OFF_H;

    float *pH1, *pHeli;
    cudaGetSymbolAddress((void**)&pH1, g_H1);
    cudaGetSymbolAddress((void**)&pHeli, g_heli);

    // fork from capture stream
    cudaEventRecord(g_sr.fork, 0);

    // side: fill from t=0, overlapping everything (patch region disjoint)
    cudaStreamWaitEvent(g_sr.s_side, g_sr.fork, 0);
    zev_zero<<<296, 256, 0, g_sr.s_side>>>(oZev);
    cudaEventRecord(g_sr.ev_z, g_sr.s_side);

    // chain prefix on s_a
    cudaStreamWaitEvent(g_sr.s_a, g_sr.fork, 0);
    prep_k<<<251, 128, 0, g_sr.s_a>>>(adj, w_m, W_beta, epoch, epochs);
    fuseA<<<125, 256, 0, g_sr.s_a>>>(bows, W_g1, pH1);
    fuseB<<<125, 256, 0, g_sr.s_a>>>(pH1, W_g2, W_h1, b_h1, W_h2, b_h2, oH, pHeli);
    cudaEventRecord(g_sr.ev3, g_sr.s_a);

    // tail: doc on s_b (needs fuseB outputs incl. ynorm2)
    cudaStreamWaitEvent(g_sr.s_b, g_sr.ev3, 0);
    doc_k<<<ND, 512, 0, g_sr.s_b>>>(masks, oH, pHeli,
                                    W_mu2, b_mu2, W_eta2, b_eta2, W_gm2, b_gm2,
                                    img, W_m1, b_m1, W_m2, b_m2,
                                    oLam, oEta, oGamma, oBeta);
    cudaEventRecord(g_sr.ev_doc, g_sr.s_b);

    // zgemm on s_a (needs heli only)
    {
        dim3 grid((NW + 63) / 64, (NW + 63) / 64);
        dim3 block(16, 16);
        gemm_nt_relu<<<grid, block, 0, g_sr.s_a>>>(pHeli, oZ, NW, NF);
    }

    // patch: needs Z_ (in-order on s_a) + kci (ev_doc); disjoint from fill.
    cudaStreamWaitEvent(g_sr.s_a, g_sr.ev_doc, 0);
    zev_patch<<<2500, 256, 0, g_sr.s_a>>>(oZ, oZev);
    cudaEventRecord(g_sr.ev_final, g_sr.s_a);

    // join
    cudaStreamWaitEvent(0, g_sr.ev_final, 0);
    cudaStreamWaitEvent(0, g_sr.ev_z, 0);
}